// round 14
// baseline (speedup 1.0000x reference)
#include <cstdint>
#include <cuda_runtime.h>
#include <cuda_fp16.h>
#include <cuda_bf16.h>
#include <math.h>

// Problem constants (fixed by the dataset)
#define NN      100000
#define NPAD    100096          // 782 * 128
#define NB      391             // (NN + 255) / 256
#define SLOTS   64              // per-node edge bucket (P(deg>=64) ~ 1e-20)
#define F_IN    256
#define H2      128
#define H1      64
#define NCLS    10

// ---------------------------------------------------------------------------
// Scratch (device globals; no runtime alloc)
// ---------------------------------------------------------------------------
__device__ float  g_dinv [NPAD];
__device__ int    g_cnt  [NPAD];
__device__ int    g_esrc [(size_t)NPAD * SLOTS];   // slot-bucketed sources
__device__ __half g_w1h  [F_IN * H2];              // W1 fp16
__device__ __half g_w2h  [H2 * H1];                // W2 fp16
__device__ __half g_m1h  [(size_t)NPAD * H2];      // x @ W1 (fp16)
__device__ __half g_m1act[(size_t)NPAD * H2];      // relu(agg1 + b1) (fp16)
__device__ __half g_m2h  [(size_t)NPAD * H1];      // m1act @ W2 (fp16)
__device__ int    g_is64;

// ---------------------------------------------------------------------------
// cp.async helpers
// ---------------------------------------------------------------------------
__device__ __forceinline__ void cp_async16(unsigned int dst, const void* src, int src_size) {
    asm volatile("cp.async.cg.shared.global [%0], [%1], 16, %2;\n"
                 :: "r"(dst), "l"(src), "r"(src_size));
}
__device__ __forceinline__ void cp_async16(unsigned int dst, const void* src) {
    asm volatile("cp.async.cg.shared.global [%0], [%1], 16;\n"
                 :: "r"(dst), "l"(src));
}
__device__ __forceinline__ void cp_commit() {
    asm volatile("cp.async.commit_group;\n");
}
__device__ __forceinline__ void cp_wait_all() {
    asm volatile("cp.async.wait_group 0;\n");
}
__device__ __forceinline__ void cp_wait_1() {
    asm volatile("cp.async.wait_group 1;\n");
}

// ---------------------------------------------------------------------------
// weight conversion: W1, W2 fp32 -> fp16 (once per call, trivial)
// ---------------------------------------------------------------------------
__global__ void convert_w_kernel(const float* __restrict__ W1,
                                 const float* __restrict__ W2) {
    int i = blockIdx.x * blockDim.x + threadIdx.x;
    if (i < F_IN * H2) g_w1h[i] = __float2half(W1[i]);
    if (i < H2 * H1)   g_w2h[i] = __float2half(W2[i]);
}

// ---------------------------------------------------------------------------
// init: zero counters; block 0 detects edge_index dtype
// ---------------------------------------------------------------------------
__global__ void init_kernel(const void* __restrict__ ei) {
    int i = blockIdx.x * blockDim.x + threadIdx.x;
    if (i < NN) g_cnt[i] = 0;
    if (blockIdx.x == 0) {
        __shared__ int snz;
        if (threadIdx.x == 0) snz = 0;
        __syncthreads();
        const int* p = (const int*)ei;
        int nz = 0;
        for (int k = threadIdx.x; k < 1024; k += blockDim.x) nz |= p[2 * k + 1];
        if (nz) atomicOr(&snz, 1);
        __syncthreads();
        if (threadIdx.x == 0) g_is64 = (snz == 0) ? 1 : 0;
    }
}

__device__ __forceinline__ int load_idx(const void* ei, long long pos) {
    if (g_is64) return (int)((const long long*)ei)[pos];
    return ((const int*)ei)[pos];
}

// ---------------------------------------------------------------------------
// single-pass bucket fill + dinv
// ---------------------------------------------------------------------------
__global__ void fill_kernel(const void* __restrict__ ei, int E) {
    int e = blockIdx.x * blockDim.x + threadIdx.x;
    if (e >= E) return;
    int s = load_idx(ei, e);
    int d = load_idx(ei, (long long)E + e);
    int pos = atomicAdd(&g_cnt[d], 1);
    if (pos < SLOTS) g_esrc[(size_t)d * SLOTS + pos] = s;
}

__global__ void dinv_kernel() {
    int i = blockIdx.x * blockDim.x + threadIdx.x;
    if (i < NN) g_dinv[i] = rsqrtf((float)(g_cnt[i] + 1));   // +1 self loop
}

// ---------------------------------------------------------------------------
// mma helper
// ---------------------------------------------------------------------------
__device__ __forceinline__ void mma16816(float* c, const unsigned int* a,
                                         unsigned int b0, unsigned int b1) {
    asm volatile(
        "mma.sync.aligned.m16n8k16.row.col.f32.f16.f16.f32 "
        "{%0,%1,%2,%3}, {%4,%5,%6,%7}, {%8,%9}, {%0,%1,%2,%3};\n"
        : "+f"(c[0]), "+f"(c[1]), "+f"(c[2]), "+f"(c[3])
        : "r"(a[0]), "r"(a[1]), "r"(a[2]), "r"(a[3]), "r"(b0), "r"(b1));
}

__device__ __forceinline__ unsigned int packh2(float x, float y) {
    __half2 h = __floats2half2_rn(x, y);
    return *reinterpret_cast<unsigned int*>(&h);
}

// ---------------------------------------------------------------------------
// GEMM1 (3-stage pipeline): C[M,128](fp16) = A(fp32) @ W1h(fp16)
// cp.async: A staged fp32 -> smem convert pass -> fp16 ldmatrix layout.
// ---------------------------------------------------------------------------
#define G1_SMEM (49152 + 10240 + 26112)

__global__ __launch_bounds__(256, 2)
void gemm1_pipe_kernel(const float* __restrict__ A, __half* __restrict__ C, int M) {
    extern __shared__ __align__(16) char sm[];
    float*  As32 = reinterpret_cast<float*>(sm);              // [3][128][32]
    __half* As16 = reinterpret_cast<__half*>(sm + 49152);     // [128][40]
    __half* Bs   = reinterpret_cast<__half*>(sm + 59392);     // [3][32][136]

    const int tx    = threadIdx.x;
    const int lane  = tx & 31;
    const int warp  = tx >> 5;
    const int warpM = warp >> 1;
    const int warpN = warp & 1;
    const int row0  = blockIdx.x * 128;
    constexpr int NIT = F_IN / 32;            // 8

    float acc[2][8][4];
#pragma unroll
    for (int t = 0; t < 2; t++)
#pragma unroll
        for (int n = 0; n < 8; n++)
#pragma unroll
            for (int k = 0; k < 4; k++) acc[t][n][k] = 0.0f;

    auto load_stage = [&](int k0, int buf) {
#pragma unroll
        for (int l = 0; l < 4; ++l) {
            int idx = tx + l * 256;
            int r = idx >> 3, c = idx & 7;
            const float* src = A + (size_t)(row0 + r) * F_IN + k0 + c * 4;
            unsigned int dst = (unsigned int)__cvta_generic_to_shared(
                As32 + buf * 4096 + r * 32 + c * 4);
            cp_async16(dst, src, (row0 + r < M) ? 16 : 0);
        }
#pragma unroll
        for (int l = 0; l < 2; ++l) {
            int idx = tx + l * 256;
            int r = idx >> 4, c = idx & 15;
            const __half* src = g_w1h + (size_t)(k0 + r) * H2 + c * 8;
            unsigned int dst = (unsigned int)__cvta_generic_to_shared(
                Bs + buf * (32 * 136) + r * 136 + c * 8);
            cp_async16(dst, src);
        }
        cp_commit();
    };

    load_stage(0, 0);
    load_stage(32, 1);

#pragma unroll
    for (int it = 0; it < NIT; ++it) {
        int buf = it % 3;
        if (it == NIT - 1) cp_wait_all(); else cp_wait_1();
        __syncthreads();
        if (it + 2 < NIT) load_stage((it + 2) * 32, (it + 2) % 3);

        // convert As32[buf] -> As16 (padded [128][40])
#pragma unroll
        for (int l = 0; l < 4; ++l) {
            int idx = tx + l * 256;
            int r = idx >> 3, c = idx & 7;
            float4 v = *reinterpret_cast<const float4*>(As32 + buf * 4096 + r * 32 + c * 4);
            __half2* d = reinterpret_cast<__half2*>(As16 + r * 40 + c * 4);
            d[0] = __floats2half2_rn(v.x, v.y);
            d[1] = __floats2half2_rn(v.z, v.w);
        }
        __syncthreads();

#pragma unroll
        for (int p = 0; p < 2; ++p) {
            unsigned int a[2][4];
#pragma unroll
            for (int t = 0; t < 2; ++t) {
                const __half* ptr = As16 + (warpM * 32 + t * 16 + (lane & 15)) * 40
                                         + p * 16 + (lane >> 4) * 8;
                unsigned int sa = (unsigned int)__cvta_generic_to_shared(ptr);
                asm volatile("ldmatrix.sync.aligned.m8n8.x4.shared.b16 {%0,%1,%2,%3}, [%4];"
                             : "=r"(a[t][0]), "=r"(a[t][1]), "=r"(a[t][2]), "=r"(a[t][3])
                             : "r"(sa));
            }
            unsigned int b[8][2];
#pragma unroll
            for (int pr = 0; pr < 4; ++pr) {
                const __half* ptr = Bs + buf * (32 * 136)
                                       + (p * 16 + (lane & 15)) * 136
                                       + warpN * 64 + pr * 16 + (lane >> 4) * 8;
                unsigned int sa = (unsigned int)__cvta_generic_to_shared(ptr);
                unsigned int r0, r1, r2, r3;
                asm volatile("ldmatrix.sync.aligned.m8n8.x4.trans.shared.b16 {%0,%1,%2,%3}, [%4];"
                             : "=r"(r0), "=r"(r1), "=r"(r2), "=r"(r3)
                             : "r"(sa));
                b[pr * 2 + 0][0] = r0; b[pr * 2 + 0][1] = r1;
                b[pr * 2 + 1][0] = r2; b[pr * 2 + 1][1] = r3;
            }
#pragma unroll
            for (int t = 0; t < 2; ++t)
#pragma unroll
                for (int n = 0; n < 8; ++n)
                    mma16816(acc[t][n], a[t], b[n][0], b[n][1]);
        }
    }

#pragma unroll
    for (int t = 0; t < 2; ++t) {
        int r = row0 + warpM * 32 + t * 16 + (lane >> 2);
        int c0 = warpN * 64 + ((lane & 3) << 1);
#pragma unroll
        for (int n = 0; n < 8; ++n) {
            int c = c0 + n * 8;
            *reinterpret_cast<__half2*>(&C[(size_t)r * H2 + c]) =
                __floats2half2_rn(acc[t][n][0], acc[t][n][1]);
            *reinterpret_cast<__half2*>(&C[(size_t)(r + 8) * H2 + c]) =
                __floats2half2_rn(acc[t][n][2], acc[t][n][3]);
        }
    }
}

// ---------------------------------------------------------------------------
// GEMM2 (3-stage pipeline): C[M,64](fp16) = A[M,128](fp16) @ W2h(fp16)
// ---------------------------------------------------------------------------
__global__ __launch_bounds__(256, 2)
void gemm2_pipe_kernel(const __half* __restrict__ A, __half* __restrict__ C) {
    __shared__ __align__(16) __half As16[3][128][40];
    __shared__ __align__(16) __half Bs[3][32][72];

    const int tx    = threadIdx.x;
    const int lane  = tx & 31;
    const int warp  = tx >> 5;
    const int warpM = warp >> 1;
    const int warpN = warp & 1;
    const int row0  = blockIdx.x * 128;
    constexpr int NIT = H2 / 32;              // 4

    float acc[2][4][4];
#pragma unroll
    for (int t = 0; t < 2; t++)
#pragma unroll
        for (int n = 0; n < 4; n++)
#pragma unroll
            for (int k = 0; k < 4; k++) acc[t][n][k] = 0.0f;

    auto load_stage = [&](int k0, int buf) {
#pragma unroll
        for (int l = 0; l < 2; ++l) {
            int idx = tx + l * 256;
            int r = idx >> 2, c = idx & 3;
            const __half* src = A + (size_t)(row0 + r) * H2 + k0 + c * 8;
            unsigned int dst = (unsigned int)__cvta_generic_to_shared(
                &As16[buf][r][c * 8]);
            cp_async16(dst, src);
        }
        {
            int r = tx >> 3, c = tx & 7;
            const __half* src = g_w2h + (size_t)(k0 + r) * H1 + c * 8;
            unsigned int dst = (unsigned int)__cvta_generic_to_shared(
                &Bs[buf][r][c * 8]);
            cp_async16(dst, src);
        }
        cp_commit();
    };

    load_stage(0, 0);
    load_stage(32, 1);

#pragma unroll
    for (int it = 0; it < NIT; ++it) {
        int buf = it % 3;
        if (it == NIT - 1) cp_wait_all(); else cp_wait_1();
        __syncthreads();                      // also protects buf reuse (3-stage)
        if (it + 2 < NIT) load_stage((it + 2) * 32, (it + 2) % 3);

#pragma unroll
        for (int p = 0; p < 2; ++p) {
            unsigned int a[2][4];
#pragma unroll
            for (int t = 0; t < 2; ++t) {
                const __half* ptr = &As16[buf][warpM * 32 + t * 16 + (lane & 15)][p * 16 + (lane >> 4) * 8];
                unsigned int sa = (unsigned int)__cvta_generic_to_shared(ptr);
                asm volatile("ldmatrix.sync.aligned.m8n8.x4.shared.b16 {%0,%1,%2,%3}, [%4];"
                             : "=r"(a[t][0]), "=r"(a[t][1]), "=r"(a[t][2]), "=r"(a[t][3])
                             : "r"(sa));
            }
            unsigned int b[4][2];
#pragma unroll
            for (int pr = 0; pr < 2; ++pr) {
                const __half* ptr = &Bs[buf][p * 16 + (lane & 15)][warpN * 32 + pr * 16 + (lane >> 4) * 8];
                unsigned int sa = (unsigned int)__cvta_generic_to_shared(ptr);
                unsigned int r0, r1, r2, r3;
                asm volatile("ldmatrix.sync.aligned.m8n8.x4.trans.shared.b16 {%0,%1,%2,%3}, [%4];"
                             : "=r"(r0), "=r"(r1), "=r"(r2), "=r"(r3)
                             : "r"(sa));
                b[pr * 2 + 0][0] = r0; b[pr * 2 + 0][1] = r1;
                b[pr * 2 + 1][0] = r2; b[pr * 2 + 1][1] = r3;
            }
#pragma unroll
            for (int t = 0; t < 2; ++t)
#pragma unroll
                for (int n = 0; n < 4; ++n)
                    mma16816(acc[t][n], a[t], b[n][0], b[n][1]);
        }
    }

#pragma unroll
    for (int t = 0; t < 2; ++t) {
        int r = row0 + warpM * 32 + t * 16 + (lane >> 2);
        int c0 = warpN * 32 + ((lane & 3) << 1);
#pragma unroll
        for (int n = 0; n < 4; ++n) {
            int c = c0 + n * 8;
            *reinterpret_cast<__half2*>(&C[(size_t)r * H1 + c]) =
                __floats2half2_rn(acc[t][n][0], acc[t][n][1]);
            *reinterpret_cast<__half2*>(&C[(size_t)(r + 8) * H1 + c]) =
                __floats2half2_rn(acc[t][n][2], acc[t][n][3]);
        }
    }
}

// ---------------------------------------------------------------------------
// helpers
// ---------------------------------------------------------------------------
__device__ __forceinline__ float2 h2f(unsigned int u) {
    __half2 h = *reinterpret_cast<__half2*>(&u);
    return __half22float2(h);
}

// ---------------------------------------------------------------------------
// gather1 + bias + relu + fp16 cast: TWO warps per node, each owning 64 of
// the 128 channels. Per-edge warp-load = uint32/lane = 128 B = 1 cache line.
// Doubles warp-level parallelism vs 1-warp/node with 2-line loads.
// ---------------------------------------------------------------------------
__global__ void gather_act_kernel(const __half* __restrict__ m,
                                  const float* __restrict__ bias,
                                  __half* __restrict__ mact) {
    int gwarp = (blockIdx.x * blockDim.x + threadIdx.x) >> 5;
    int gw   = gwarp >> 1;                 // node
    int half = gwarp & 1;                  // channel half: [half*64, half*64+64)
    if (gw >= NN) return;
    int lane = threadIdx.x & 31;
    const int coff = half * 64 + lane * 2; // this lane's channel pair

    float di = g_dinv[gw];
    float wself = di * di;
    int cnt = min(g_cnt[gw], SLOTS);
    const size_t base = (size_t)gw * SLOTS;

    unsigned int rw = *reinterpret_cast<const unsigned int*>(m + (size_t)gw * H2 + coff);
    float2 f = h2f(rw);
    float2 acc = make_float2(f.x * wself, f.y * wself);

    for (int j0 = 0; j0 < cnt; j0 += 32) {
        int n = min(32, cnt - j0);
        int s = 0; float w = 0.f;
        if (lane < n) {
            s = g_esrc[base + j0 + lane];
            w = g_dinv[s] * di;
        }
        int t = 0;
        for (; t + 4 <= n; t += 4) {
            int   s0 = __shfl_sync(0xffffffffu, s, t);
            int   s1 = __shfl_sync(0xffffffffu, s, t + 1);
            int   s2 = __shfl_sync(0xffffffffu, s, t + 2);
            int   s3 = __shfl_sync(0xffffffffu, s, t + 3);
            float w0 = __shfl_sync(0xffffffffu, w, t);
            float w1 = __shfl_sync(0xffffffffu, w, t + 1);
            float w2 = __shfl_sync(0xffffffffu, w, t + 2);
            float w3 = __shfl_sync(0xffffffffu, w, t + 3);
            unsigned int u0 = *reinterpret_cast<const unsigned int*>(m + (size_t)s0 * H2 + coff);
            unsigned int u1 = *reinterpret_cast<const unsigned int*>(m + (size_t)s1 * H2 + coff);
            unsigned int u2 = *reinterpret_cast<const unsigned int*>(m + (size_t)s2 * H2 + coff);
            unsigned int u3 = *reinterpret_cast<const unsigned int*>(m + (size_t)s3 * H2 + coff);
            float2 a0;
            a0 = h2f(u0); acc.x += a0.x * w0; acc.y += a0.y * w0;
            a0 = h2f(u1); acc.x += a0.x * w1; acc.y += a0.y * w1;
            a0 = h2f(u2); acc.x += a0.x * w2; acc.y += a0.y * w2;
            a0 = h2f(u3); acc.x += a0.x * w3; acc.y += a0.y * w3;
        }
        for (; t < n; ++t) {
            int   st = __shfl_sync(0xffffffffu, s, t);
            float wt = __shfl_sync(0xffffffffu, w, t);
            unsigned int u = *reinterpret_cast<const unsigned int*>(m + (size_t)st * H2 + coff);
            float2 a0 = h2f(u);
            acc.x += a0.x * wt; acc.y += a0.y * wt;
        }
    }

    float2 bb = *reinterpret_cast<const float2*>(&bias[coff]);
    acc.x = fmaxf(acc.x + bb.x, 0.f);
    acc.y = fmaxf(acc.y + bb.y, 0.f);
    *reinterpret_cast<unsigned int*>(mact + (size_t)gw * H2 + coff) = packh2(acc.x, acc.y);
}

// ---------------------------------------------------------------------------
// gather2 + classifier + log_softmax fused: warp per node, F=64,
// per-edge broadcast, uint32 loads (1 line/warp-load), unroll x8.
// ---------------------------------------------------------------------------
__global__ void gather_final_kernel(const __half* __restrict__ m,
                                    const float* __restrict__ b2,
                                    const float* __restrict__ Wl,
                                    const float* __restrict__ bl,
                                    float* __restrict__ out) {
    __shared__ float sW[H1 * NCLS];
    __shared__ float sb[NCLS];
    for (int i = threadIdx.x; i < H1 * NCLS; i += blockDim.x) sW[i] = Wl[i];
    if (threadIdx.x < NCLS) sb[threadIdx.x] = bl[threadIdx.x];
    __syncthreads();

    int gw = (blockIdx.x * blockDim.x + threadIdx.x) >> 5;
    if (gw >= NN) return;
    int lane = threadIdx.x & 31;

    float di = g_dinv[gw];
    float wself = di * di;
    int cnt = min(g_cnt[gw], SLOTS);
    const size_t base = (size_t)gw * SLOTS;

    unsigned int rw = *reinterpret_cast<const unsigned int*>(m + (size_t)gw * H1 + lane * 2);
    float2 f = h2f(rw);
    float2 acc = make_float2(f.x * wself, f.y * wself);

    for (int j0 = 0; j0 < cnt; j0 += 32) {
        int n = min(32, cnt - j0);
        int s = 0; float w = 0.f;
        if (lane < n) {
            s = g_esrc[base + j0 + lane];
            w = g_dinv[s] * di;
        }
        int t = 0;
        for (; t + 8 <= n; t += 8) {
            int   si[8]; float wi[8];
#pragma unroll
            for (int q = 0; q < 8; ++q) {
                si[q] = __shfl_sync(0xffffffffu, s, t + q);
                wi[q] = __shfl_sync(0xffffffffu, w, t + q);
            }
            unsigned int ui[8];
#pragma unroll
            for (int q = 0; q < 8; ++q)
                ui[q] = *reinterpret_cast<const unsigned int*>(m + (size_t)si[q] * H1 + lane * 2);
#pragma unroll
            for (int q = 0; q < 8; ++q) {
                float2 a0 = h2f(ui[q]);
                acc.x += a0.x * wi[q]; acc.y += a0.y * wi[q];
            }
        }
        for (; t + 4 <= n; t += 4) {
            int   s0 = __shfl_sync(0xffffffffu, s, t);
            int   s1 = __shfl_sync(0xffffffffu, s, t + 1);
            int   s2 = __shfl_sync(0xffffffffu, s, t + 2);
            int   s3 = __shfl_sync(0xffffffffu, s, t + 3);
            float w0 = __shfl_sync(0xffffffffu, w, t);
            float w1 = __shfl_sync(0xffffffffu, w, t + 1);
            float w2 = __shfl_sync(0xffffffffu, w, t + 2);
            float w3 = __shfl_sync(0xffffffffu, w, t + 3);
            unsigned int u0 = *reinterpret_cast<const unsigned int*>(m + (size_t)s0 * H1 + lane * 2);
            unsigned int u1 = *reinterpret_cast<const unsigned int*>(m + (size_t)s1 * H1 + lane * 2);
            unsigned int u2 = *reinterpret_cast<const unsigned int*>(m + (size_t)s2 * H1 + lane * 2);
            unsigned int u3 = *reinterpret_cast<const unsigned int*>(m + (size_t)s3 * H1 + lane * 2);
            float2 a0;
            a0 = h2f(u0); acc.x += a0.x * w0; acc.y += a0.y * w0;
            a0 = h2f(u1); acc.x += a0.x * w1; acc.y += a0.y * w1;
            a0 = h2f(u2); acc.x += a0.x * w2; acc.y += a0.y * w2;
            a0 = h2f(u3); acc.x += a0.x * w3; acc.y += a0.y * w3;
        }
        for (; t < n; ++t) {
            int   st = __shfl_sync(0xffffffffu, s, t);
            float wt = __shfl_sync(0xffffffffu, w, t);
            unsigned int u = *reinterpret_cast<const unsigned int*>(m + (size_t)st * H1 + lane * 2);
            float2 a0 = h2f(u);
            acc.x += a0.x * wt; acc.y += a0.y * wt;
        }
    }

    float2 bb = *reinterpret_cast<const float2*>(&b2[lane * 2]);
    float h0 = fmaxf(acc.x + bb.x, 0.f);
    float h1 = fmaxf(acc.y + bb.y, 0.f);

    float logit[NCLS];
#pragma unroll
    for (int c = 0; c < NCLS; c++) {
        float p = h0 * sW[(lane * 2) * NCLS + c] + h1 * sW[(lane * 2 + 1) * NCLS + c];
#pragma unroll
        for (int o = 16; o; o >>= 1) p += __shfl_xor_sync(0xffffffffu, p, o);
        logit[c] = p + sb[c];
    }
    float mx = logit[0];
#pragma unroll
    for (int c = 1; c < NCLS; c++) mx = fmaxf(mx, logit[c]);
    float se = 0.f;
#pragma unroll
    for (int c = 0; c < NCLS; c++) se += expf(logit[c] - mx);
    float lse = mx + logf(se);
    if (lane < NCLS) out[(size_t)gw * NCLS + lane] = logit[lane] - lse;
}

// ---------------------------------------------------------------------------
// Launcher (R12 topology): bucket build on side stream, hidden under GEMM1.
// ---------------------------------------------------------------------------
extern "C" void kernel_launch(void* const* d_in, const int* in_sizes, int n_in,
                              void* d_out, int out_size) {
    const float* x  = (const float*)d_in[0];
    const void*  ei = d_in[1];
    const float* W1 = (const float*)d_in[2];
    const float* b1 = (const float*)d_in[3];
    const float* W2 = (const float*)d_in[4];
    const float* b2 = (const float*)d_in[5];
    const float* Wl = (const float*)d_in[6];
    const float* bl = (const float*)d_in[7];
    float* out = (float*)d_out;
    const int E = in_sizes[1] / 2;

    __half* p_m1  = nullptr; cudaGetSymbolAddress((void**)&p_m1,  g_m1h);
    __half* p_m1a = nullptr; cudaGetSymbolAddress((void**)&p_m1a, g_m1act);
    __half* p_m2  = nullptr; cudaGetSymbolAddress((void**)&p_m2,  g_m2h);

    static cudaStream_t s_csr = nullptr;
    static cudaEvent_t  ev_fork = nullptr, ev_join = nullptr;
    if (s_csr == nullptr) {
        cudaStreamCreateWithFlags(&s_csr, cudaStreamNonBlocking);
        cudaEventCreateWithFlags(&ev_fork, cudaEventDisableTiming);
        cudaEventCreateWithFlags(&ev_join, cudaEventDisableTiming);
        cudaFuncSetAttribute(gemm1_pipe_kernel,
                             cudaFuncAttributeMaxDynamicSharedMemorySize, G1_SMEM);
    }

    // fork: bucket build chain on side stream
    cudaEventRecord(ev_fork, 0);
    cudaStreamWaitEvent(s_csr, ev_fork, 0);
    init_kernel<<<NB, 256, 0, s_csr>>>(ei);
    fill_kernel<<<(E + 255) / 256, 256, 0, s_csr>>>(ei, E);
    dinv_kernel<<<NB, 256, 0, s_csr>>>();
    cudaEventRecord(ev_join, s_csr);

    // main stream: weights + GEMM1 (independent of edge structure)
    convert_w_kernel<<<(F_IN * H2 + 255) / 256, 256>>>(W1, W2);
    gemm1_pipe_kernel<<<NPAD / 128, 256, G1_SMEM>>>(x, p_m1, NN);

    // join: gather needs both GEMM1 output and edge buckets
    cudaStreamWaitEvent(0, ev_join, 0);
    gather_act_kernel<<<(NN * 2 * 32 + 255) / 256, 256>>>(p_m1, b1, p_m1a);

    // layer 2 + fused classifier
    gemm2_pipe_kernel<<<NPAD / 128, 256>>>(p_m1a, p_m2);
    gather_final_kernel<<<(NN + 7) / 8, 256>>>(p_m2, b2, Wl, bl, out);
}

// round 15
// speedup vs baseline: 1.1639x; 1.1639x over previous
#include <cstdint>
#include <cuda_runtime.h>
#include <cuda_fp16.h>
#include <cuda_bf16.h>
#include <math.h>

// Problem constants (fixed by the dataset)
#define NN      100000
#define NPAD    100096          // 782 * 128
#define NB      391             // (NN + 255) / 256
#define SLOTS   64              // per-node edge bucket (P(deg>=64) ~ 1e-20)
#define F_IN    256
#define H2      128
#define H1      64
#define NCLS    10

// ---------------------------------------------------------------------------
// Scratch (device globals; no runtime alloc)
// ---------------------------------------------------------------------------
__device__ float  g_dinv [NPAD];
__device__ int    g_cnt  [NPAD];
__device__ int    g_esrc [(size_t)NPAD * SLOTS];   // slot-bucketed sources
__device__ __half g_w1h  [F_IN * H2];              // W1 fp16
__device__ __half g_w2h  [H2 * H1];                // W2 fp16
__device__ __half g_m1h  [(size_t)NPAD * H2];      // x @ W1 (fp16)
__device__ __half g_m1act[(size_t)NPAD * H2];      // relu(agg1 + b1) (fp16)
__device__ __half g_m2h  [(size_t)NPAD * H1];      // m1act @ W2 (fp16)
__device__ int    g_is64;

// ---------------------------------------------------------------------------
// cp.async helpers
// ---------------------------------------------------------------------------
__device__ __forceinline__ void cp_async16(unsigned int dst, const void* src, int src_size) {
    asm volatile("cp.async.cg.shared.global [%0], [%1], 16, %2;\n"
                 :: "r"(dst), "l"(src), "r"(src_size));
}
__device__ __forceinline__ void cp_async16(unsigned int dst, const void* src) {
    asm volatile("cp.async.cg.shared.global [%0], [%1], 16;\n"
                 :: "r"(dst), "l"(src));
}
__device__ __forceinline__ void cp_commit() {
    asm volatile("cp.async.commit_group;\n");
}
__device__ __forceinline__ void cp_wait_all() {
    asm volatile("cp.async.wait_group 0;\n");
}
__device__ __forceinline__ void cp_wait_1() {
    asm volatile("cp.async.wait_group 1;\n");
}

// ---------------------------------------------------------------------------
// weight conversion: W1, W2 fp32 -> fp16 (once per call, trivial)
// ---------------------------------------------------------------------------
__global__ void convert_w_kernel(const float* __restrict__ W1,
                                 const float* __restrict__ W2) {
    int i = blockIdx.x * blockDim.x + threadIdx.x;
    if (i < F_IN * H2) g_w1h[i] = __float2half(W1[i]);
    if (i < H2 * H1)   g_w2h[i] = __float2half(W2[i]);
}

// ---------------------------------------------------------------------------
// init: zero counters; block 0 detects edge_index dtype
// ---------------------------------------------------------------------------
__global__ void init_kernel(const void* __restrict__ ei) {
    int i = blockIdx.x * blockDim.x + threadIdx.x;
    if (i < NN) g_cnt[i] = 0;
    if (blockIdx.x == 0) {
        __shared__ int snz;
        if (threadIdx.x == 0) snz = 0;
        __syncthreads();
        const int* p = (const int*)ei;
        int nz = 0;
        for (int k = threadIdx.x; k < 1024; k += blockDim.x) nz |= p[2 * k + 1];
        if (nz) atomicOr(&snz, 1);
        __syncthreads();
        if (threadIdx.x == 0) g_is64 = (snz == 0) ? 1 : 0;
    }
}

__device__ __forceinline__ int load_idx(const void* ei, long long pos) {
    if (g_is64) return (int)((const long long*)ei)[pos];
    return ((const int*)ei)[pos];
}

// ---------------------------------------------------------------------------
// single-pass bucket fill + dinv
// ---------------------------------------------------------------------------
__global__ void fill_kernel(const void* __restrict__ ei, int E) {
    int e = blockIdx.x * blockDim.x + threadIdx.x;
    if (e >= E) return;
    int s = load_idx(ei, e);
    int d = load_idx(ei, (long long)E + e);
    int pos = atomicAdd(&g_cnt[d], 1);
    if (pos < SLOTS) g_esrc[(size_t)d * SLOTS + pos] = s;
}

__global__ void dinv_kernel() {
    int i = blockIdx.x * blockDim.x + threadIdx.x;
    if (i < NN) g_dinv[i] = rsqrtf((float)(g_cnt[i] + 1));   // +1 self loop
}

// ---------------------------------------------------------------------------
// mma helper
// ---------------------------------------------------------------------------
__device__ __forceinline__ void mma16816(float* c, const unsigned int* a,
                                         unsigned int b0, unsigned int b1) {
    asm volatile(
        "mma.sync.aligned.m16n8k16.row.col.f32.f16.f16.f32 "
        "{%0,%1,%2,%3}, {%4,%5,%6,%7}, {%8,%9}, {%0,%1,%2,%3};\n"
        : "+f"(c[0]), "+f"(c[1]), "+f"(c[2]), "+f"(c[3])
        : "r"(a[0]), "r"(a[1]), "r"(a[2]), "r"(a[3]), "r"(b0), "r"(b1));
}

__device__ __forceinline__ unsigned int packh2(float x, float y) {
    __half2 h = __floats2half2_rn(x, y);
    return *reinterpret_cast<unsigned int*>(&h);
}

// ---------------------------------------------------------------------------
// GEMM1 (3-stage pipeline): C[M,128](fp16) = A(fp32) @ W1h(fp16)
// cp.async: A staged fp32 -> smem convert pass -> fp16 ldmatrix layout.
// ---------------------------------------------------------------------------
#define G1_SMEM (49152 + 10240 + 26112)

__global__ __launch_bounds__(256, 2)
void gemm1_pipe_kernel(const float* __restrict__ A, __half* __restrict__ C, int M) {
    extern __shared__ __align__(16) char sm[];
    float*  As32 = reinterpret_cast<float*>(sm);              // [3][128][32]
    __half* As16 = reinterpret_cast<__half*>(sm + 49152);     // [128][40]
    __half* Bs   = reinterpret_cast<__half*>(sm + 59392);     // [3][32][136]

    const int tx    = threadIdx.x;
    const int lane  = tx & 31;
    const int warp  = tx >> 5;
    const int warpM = warp >> 1;
    const int warpN = warp & 1;
    const int row0  = blockIdx.x * 128;
    constexpr int NIT = F_IN / 32;            // 8

    float acc[2][8][4];
#pragma unroll
    for (int t = 0; t < 2; t++)
#pragma unroll
        for (int n = 0; n < 8; n++)
#pragma unroll
            for (int k = 0; k < 4; k++) acc[t][n][k] = 0.0f;

    auto load_stage = [&](int k0, int buf) {
#pragma unroll
        for (int l = 0; l < 4; ++l) {
            int idx = tx + l * 256;
            int r = idx >> 3, c = idx & 7;
            const float* src = A + (size_t)(row0 + r) * F_IN + k0 + c * 4;
            unsigned int dst = (unsigned int)__cvta_generic_to_shared(
                As32 + buf * 4096 + r * 32 + c * 4);
            cp_async16(dst, src, (row0 + r < M) ? 16 : 0);
        }
#pragma unroll
        for (int l = 0; l < 2; ++l) {
            int idx = tx + l * 256;
            int r = idx >> 4, c = idx & 15;
            const __half* src = g_w1h + (size_t)(k0 + r) * H2 + c * 8;
            unsigned int dst = (unsigned int)__cvta_generic_to_shared(
                Bs + buf * (32 * 136) + r * 136 + c * 8);
            cp_async16(dst, src);
        }
        cp_commit();
    };

    load_stage(0, 0);
    load_stage(32, 1);

#pragma unroll
    for (int it = 0; it < NIT; ++it) {
        int buf = it % 3;
        if (it == NIT - 1) cp_wait_all(); else cp_wait_1();
        __syncthreads();
        if (it + 2 < NIT) load_stage((it + 2) * 32, (it + 2) % 3);

        // convert As32[buf] -> As16 (padded [128][40])
#pragma unroll
        for (int l = 0; l < 4; ++l) {
            int idx = tx + l * 256;
            int r = idx >> 3, c = idx & 7;
            float4 v = *reinterpret_cast<const float4*>(As32 + buf * 4096 + r * 32 + c * 4);
            __half2* d = reinterpret_cast<__half2*>(As16 + r * 40 + c * 4);
            d[0] = __floats2half2_rn(v.x, v.y);
            d[1] = __floats2half2_rn(v.z, v.w);
        }
        __syncthreads();

#pragma unroll
        for (int p = 0; p < 2; ++p) {
            unsigned int a[2][4];
#pragma unroll
            for (int t = 0; t < 2; ++t) {
                const __half* ptr = As16 + (warpM * 32 + t * 16 + (lane & 15)) * 40
                                         + p * 16 + (lane >> 4) * 8;
                unsigned int sa = (unsigned int)__cvta_generic_to_shared(ptr);
                asm volatile("ldmatrix.sync.aligned.m8n8.x4.shared.b16 {%0,%1,%2,%3}, [%4];"
                             : "=r"(a[t][0]), "=r"(a[t][1]), "=r"(a[t][2]), "=r"(a[t][3])
                             : "r"(sa));
            }
            unsigned int b[8][2];
#pragma unroll
            for (int pr = 0; pr < 4; ++pr) {
                const __half* ptr = Bs + buf * (32 * 136)
                                       + (p * 16 + (lane & 15)) * 136
                                       + warpN * 64 + pr * 16 + (lane >> 4) * 8;
                unsigned int sa = (unsigned int)__cvta_generic_to_shared(ptr);
                unsigned int r0, r1, r2, r3;
                asm volatile("ldmatrix.sync.aligned.m8n8.x4.trans.shared.b16 {%0,%1,%2,%3}, [%4];"
                             : "=r"(r0), "=r"(r1), "=r"(r2), "=r"(r3)
                             : "r"(sa));
                b[pr * 2 + 0][0] = r0; b[pr * 2 + 0][1] = r1;
                b[pr * 2 + 1][0] = r2; b[pr * 2 + 1][1] = r3;
            }
#pragma unroll
            for (int t = 0; t < 2; ++t)
#pragma unroll
                for (int n = 0; n < 8; ++n)
                    mma16816(acc[t][n], a[t], b[n][0], b[n][1]);
        }
    }

#pragma unroll
    for (int t = 0; t < 2; ++t) {
        int r = row0 + warpM * 32 + t * 16 + (lane >> 2);
        int c0 = warpN * 64 + ((lane & 3) << 1);
#pragma unroll
        for (int n = 0; n < 8; ++n) {
            int c = c0 + n * 8;
            *reinterpret_cast<__half2*>(&C[(size_t)r * H2 + c]) =
                __floats2half2_rn(acc[t][n][0], acc[t][n][1]);
            *reinterpret_cast<__half2*>(&C[(size_t)(r + 8) * H2 + c]) =
                __floats2half2_rn(acc[t][n][2], acc[t][n][3]);
        }
    }
}

// ---------------------------------------------------------------------------
// GEMM2 (3-stage pipeline): C[M,64](fp16) = A[M,128](fp16) @ W2h(fp16)
// ---------------------------------------------------------------------------
__global__ __launch_bounds__(256, 2)
void gemm2_pipe_kernel(const __half* __restrict__ A, __half* __restrict__ C) {
    __shared__ __align__(16) __half As16[3][128][40];
    __shared__ __align__(16) __half Bs[3][32][72];

    const int tx    = threadIdx.x;
    const int lane  = tx & 31;
    const int warp  = tx >> 5;
    const int warpM = warp >> 1;
    const int warpN = warp & 1;
    const int row0  = blockIdx.x * 128;
    constexpr int NIT = H2 / 32;              // 4

    float acc[2][4][4];
#pragma unroll
    for (int t = 0; t < 2; t++)
#pragma unroll
        for (int n = 0; n < 4; n++)
#pragma unroll
            for (int k = 0; k < 4; k++) acc[t][n][k] = 0.0f;

    auto load_stage = [&](int k0, int buf) {
#pragma unroll
        for (int l = 0; l < 2; ++l) {
            int idx = tx + l * 256;
            int r = idx >> 2, c = idx & 3;
            const __half* src = A + (size_t)(row0 + r) * H2 + k0 + c * 8;
            unsigned int dst = (unsigned int)__cvta_generic_to_shared(
                &As16[buf][r][c * 8]);
            cp_async16(dst, src);
        }
        {
            int r = tx >> 3, c = tx & 7;
            const __half* src = g_w2h + (size_t)(k0 + r) * H1 + c * 8;
            unsigned int dst = (unsigned int)__cvta_generic_to_shared(
                &Bs[buf][r][c * 8]);
            cp_async16(dst, src);
        }
        cp_commit();
    };

    load_stage(0, 0);
    load_stage(32, 1);

#pragma unroll
    for (int it = 0; it < NIT; ++it) {
        int buf = it % 3;
        if (it == NIT - 1) cp_wait_all(); else cp_wait_1();
        __syncthreads();                      // also protects buf reuse (3-stage)
        if (it + 2 < NIT) load_stage((it + 2) * 32, (it + 2) % 3);

#pragma unroll
        for (int p = 0; p < 2; ++p) {
            unsigned int a[2][4];
#pragma unroll
            for (int t = 0; t < 2; ++t) {
                const __half* ptr = &As16[buf][warpM * 32 + t * 16 + (lane & 15)][p * 16 + (lane >> 4) * 8];
                unsigned int sa = (unsigned int)__cvta_generic_to_shared(ptr);
                asm volatile("ldmatrix.sync.aligned.m8n8.x4.shared.b16 {%0,%1,%2,%3}, [%4];"
                             : "=r"(a[t][0]), "=r"(a[t][1]), "=r"(a[t][2]), "=r"(a[t][3])
                             : "r"(sa));
            }
            unsigned int b[4][2];
#pragma unroll
            for (int pr = 0; pr < 2; ++pr) {
                const __half* ptr = &Bs[buf][p * 16 + (lane & 15)][warpN * 32 + pr * 16 + (lane >> 4) * 8];
                unsigned int sa = (unsigned int)__cvta_generic_to_shared(ptr);
                unsigned int r0, r1, r2, r3;
                asm volatile("ldmatrix.sync.aligned.m8n8.x4.trans.shared.b16 {%0,%1,%2,%3}, [%4];"
                             : "=r"(r0), "=r"(r1), "=r"(r2), "=r"(r3)
                             : "r"(sa));
                b[pr * 2 + 0][0] = r0; b[pr * 2 + 0][1] = r1;
                b[pr * 2 + 1][0] = r2; b[pr * 2 + 1][1] = r3;
            }
#pragma unroll
            for (int t = 0; t < 2; ++t)
#pragma unroll
                for (int n = 0; n < 4; ++n)
                    mma16816(acc[t][n], a[t], b[n][0], b[n][1]);
        }
    }

#pragma unroll
    for (int t = 0; t < 2; ++t) {
        int r = row0 + warpM * 32 + t * 16 + (lane >> 2);
        int c0 = warpN * 32 + ((lane & 3) << 1);
#pragma unroll
        for (int n = 0; n < 4; ++n) {
            int c = c0 + n * 8;
            *reinterpret_cast<__half2*>(&C[(size_t)r * H1 + c]) =
                __floats2half2_rn(acc[t][n][0], acc[t][n][1]);
            *reinterpret_cast<__half2*>(&C[(size_t)(r + 8) * H1 + c]) =
                __floats2half2_rn(acc[t][n][2], acc[t][n][3]);
        }
    }
}

// ---------------------------------------------------------------------------
// helpers
// ---------------------------------------------------------------------------
__device__ __forceinline__ float2 h2f(unsigned int u) {
    __half2 h = *reinterpret_cast<__half2*>(&u);
    return __half22float2(h);
}

// ---------------------------------------------------------------------------
// gather1 + bias + relu + fp16 cast: warp per node, F=128, uint2 loads,
// unroll x4 (measured-optimal configuration). Weights from g_dinv on the fly.
// ---------------------------------------------------------------------------
__global__ void gather_act_kernel(const __half* __restrict__ m,
                                  const float* __restrict__ bias,
                                  __half* __restrict__ mact) {
    int gw = (blockIdx.x * blockDim.x + threadIdx.x) >> 5;
    if (gw >= NN) return;
    int lane = threadIdx.x & 31;

    float di = g_dinv[gw];
    float wself = di * di;
    int cnt = min(g_cnt[gw], SLOTS);
    const size_t base = (size_t)gw * SLOTS;

    uint2 rw = *reinterpret_cast<const uint2*>(m + (size_t)gw * H2 + lane * 4);
    float2 f0 = h2f(rw.x), f1 = h2f(rw.y);
    float4 acc = make_float4(f0.x * wself, f0.y * wself, f1.x * wself, f1.y * wself);

    for (int j0 = 0; j0 < cnt; j0 += 32) {
        int n = min(32, cnt - j0);
        int s = 0; float w = 0.f;
        if (lane < n) {
            s = g_esrc[base + j0 + lane];
            w = g_dinv[s] * di;
        }
        int t = 0;
        for (; t + 4 <= n; t += 4) {
            int   s0 = __shfl_sync(0xffffffffu, s, t);
            int   s1 = __shfl_sync(0xffffffffu, s, t + 1);
            int   s2 = __shfl_sync(0xffffffffu, s, t + 2);
            int   s3 = __shfl_sync(0xffffffffu, s, t + 3);
            float w0 = __shfl_sync(0xffffffffu, w, t);
            float w1 = __shfl_sync(0xffffffffu, w, t + 1);
            float w2 = __shfl_sync(0xffffffffu, w, t + 2);
            float w3 = __shfl_sync(0xffffffffu, w, t + 3);
            uint2 u0 = *reinterpret_cast<const uint2*>(m + (size_t)s0 * H2 + lane * 4);
            uint2 u1 = *reinterpret_cast<const uint2*>(m + (size_t)s1 * H2 + lane * 4);
            uint2 u2 = *reinterpret_cast<const uint2*>(m + (size_t)s2 * H2 + lane * 4);
            uint2 u3 = *reinterpret_cast<const uint2*>(m + (size_t)s3 * H2 + lane * 4);
            float2 a0, a1;
            a0 = h2f(u0.x); a1 = h2f(u0.y);
            acc.x += a0.x * w0; acc.y += a0.y * w0; acc.z += a1.x * w0; acc.w += a1.y * w0;
            a0 = h2f(u1.x); a1 = h2f(u1.y);
            acc.x += a0.x * w1; acc.y += a0.y * w1; acc.z += a1.x * w1; acc.w += a1.y * w1;
            a0 = h2f(u2.x); a1 = h2f(u2.y);
            acc.x += a0.x * w2; acc.y += a0.y * w2; acc.z += a1.x * w2; acc.w += a1.y * w2;
            a0 = h2f(u3.x); a1 = h2f(u3.y);
            acc.x += a0.x * w3; acc.y += a0.y * w3; acc.z += a1.x * w3; acc.w += a1.y * w3;
        }
        for (; t < n; ++t) {
            int   st = __shfl_sync(0xffffffffu, s, t);
            float wt = __shfl_sync(0xffffffffu, w, t);
            uint2 u = *reinterpret_cast<const uint2*>(m + (size_t)st * H2 + lane * 4);
            float2 a0 = h2f(u.x), a1 = h2f(u.y);
            acc.x += a0.x * wt; acc.y += a0.y * wt;
            acc.z += a1.x * wt; acc.w += a1.y * wt;
        }
    }

    float4 bb = *reinterpret_cast<const float4*>(&bias[lane * 4]);
    acc.x = fmaxf(acc.x + bb.x, 0.f);
    acc.y = fmaxf(acc.y + bb.y, 0.f);
    acc.z = fmaxf(acc.z + bb.z, 0.f);
    acc.w = fmaxf(acc.w + bb.w, 0.f);
    uint2 outw;
    outw.x = packh2(acc.x, acc.y);
    outw.y = packh2(acc.z, acc.w);
    *reinterpret_cast<uint2*>(mact + (size_t)gw * H2 + lane * 4) = outw;
}

// ---------------------------------------------------------------------------
// gather2 + classifier + log_softmax fused: warp per node, F=64,
// per-edge broadcast, uint32 loads, unroll x4 (measured-optimal).
// ---------------------------------------------------------------------------
__global__ void gather_final_kernel(const __half* __restrict__ m,
                                    const float* __restrict__ b2,
                                    const float* __restrict__ Wl,
                                    const float* __restrict__ bl,
                                    float* __restrict__ out) {
    __shared__ float sW[H1 * NCLS];
    __shared__ float sb[NCLS];
    for (int i = threadIdx.x; i < H1 * NCLS; i += blockDim.x) sW[i] = Wl[i];
    if (threadIdx.x < NCLS) sb[threadIdx.x] = bl[threadIdx.x];
    __syncthreads();

    int gw = (blockIdx.x * blockDim.x + threadIdx.x) >> 5;
    if (gw >= NN) return;
    int lane = threadIdx.x & 31;

    float di = g_dinv[gw];
    float wself = di * di;
    int cnt = min(g_cnt[gw], SLOTS);
    const size_t base = (size_t)gw * SLOTS;

    unsigned int rw = *reinterpret_cast<const unsigned int*>(m + (size_t)gw * H1 + lane * 2);
    float2 f = h2f(rw);
    float2 acc = make_float2(f.x * wself, f.y * wself);

    for (int j0 = 0; j0 < cnt; j0 += 32) {
        int n = min(32, cnt - j0);
        int s = 0; float w = 0.f;
        if (lane < n) {
            s = g_esrc[base + j0 + lane];
            w = g_dinv[s] * di;
        }
        int t = 0;
        for (; t + 4 <= n; t += 4) {
            int   s0 = __shfl_sync(0xffffffffu, s, t);
            int   s1 = __shfl_sync(0xffffffffu, s, t + 1);
            int   s2 = __shfl_sync(0xffffffffu, s, t + 2);
            int   s3 = __shfl_sync(0xffffffffu, s, t + 3);
            float w0 = __shfl_sync(0xffffffffu, w, t);
            float w1 = __shfl_sync(0xffffffffu, w, t + 1);
            float w2 = __shfl_sync(0xffffffffu, w, t + 2);
            float w3 = __shfl_sync(0xffffffffu, w, t + 3);
            unsigned int u0 = *reinterpret_cast<const unsigned int*>(m + (size_t)s0 * H1 + lane * 2);
            unsigned int u1 = *reinterpret_cast<const unsigned int*>(m + (size_t)s1 * H1 + lane * 2);
            unsigned int u2 = *reinterpret_cast<const unsigned int*>(m + (size_t)s2 * H1 + lane * 2);
            unsigned int u3 = *reinterpret_cast<const unsigned int*>(m + (size_t)s3 * H1 + lane * 2);
            float2 a0;
            a0 = h2f(u0); acc.x += a0.x * w0; acc.y += a0.y * w0;
            a0 = h2f(u1); acc.x += a0.x * w1; acc.y += a0.y * w1;
            a0 = h2f(u2); acc.x += a0.x * w2; acc.y += a0.y * w2;
            a0 = h2f(u3); acc.x += a0.x * w3; acc.y += a0.y * w3;
        }
        for (; t < n; ++t) {
            int   st = __shfl_sync(0xffffffffu, s, t);
            float wt = __shfl_sync(0xffffffffu, w, t);
            unsigned int u = *reinterpret_cast<const unsigned int*>(m + (size_t)st * H1 + lane * 2);
            float2 a0 = h2f(u);
            acc.x += a0.x * wt; acc.y += a0.y * wt;
        }
    }

    float2 bb = *reinterpret_cast<const float2*>(&b2[lane * 2]);
    float h0 = fmaxf(acc.x + bb.x, 0.f);
    float h1 = fmaxf(acc.y + bb.y, 0.f);

    float logit[NCLS];
#pragma unroll
    for (int c = 0; c < NCLS; c++) {
        float p = h0 * sW[(lane * 2) * NCLS + c] + h1 * sW[(lane * 2 + 1) * NCLS + c];
#pragma unroll
        for (int o = 16; o; o >>= 1) p += __shfl_xor_sync(0xffffffffu, p, o);
        logit[c] = p + sb[c];
    }
    float mx = logit[0];
#pragma unroll
    for (int c = 1; c < NCLS; c++) mx = fmaxf(mx, logit[c]);
    float se = 0.f;
#pragma unroll
    for (int c = 0; c < NCLS; c++) se += expf(logit[c] - mx);
    float lse = mx + logf(se);
    if (lane < NCLS) out[(size_t)gw * NCLS + lane] = logit[lane] - lse;
}

// ---------------------------------------------------------------------------
// Launcher: bucket build forked onto side stream, hidden under GEMM1.
// ---------------------------------------------------------------------------
extern "C" void kernel_launch(void* const* d_in, const int* in_sizes, int n_in,
                              void* d_out, int out_size) {
    const float* x  = (const float*)d_in[0];
    const void*  ei = d_in[1];
    const float* W1 = (const float*)d_in[2];
    const float* b1 = (const float*)d_in[3];
    const float* W2 = (const float*)d_in[4];
    const float* b2 = (const float*)d_in[5];
    const float* Wl = (const float*)d_in[6];
    const float* bl = (const float*)d_in[7];
    float* out = (float*)d_out;
    const int E = in_sizes[1] / 2;

    __half* p_m1  = nullptr; cudaGetSymbolAddress((void**)&p_m1,  g_m1h);
    __half* p_m1a = nullptr; cudaGetSymbolAddress((void**)&p_m1a, g_m1act);
    __half* p_m2  = nullptr; cudaGetSymbolAddress((void**)&p_m2,  g_m2h);

    static cudaStream_t s_csr = nullptr;
    static cudaEvent_t  ev_fork = nullptr, ev_join = nullptr;
    if (s_csr == nullptr) {
        cudaStreamCreateWithFlags(&s_csr, cudaStreamNonBlocking);
        cudaEventCreateWithFlags(&ev_fork, cudaEventDisableTiming);
        cudaEventCreateWithFlags(&ev_join, cudaEventDisableTiming);
        cudaFuncSetAttribute(gemm1_pipe_kernel,
                             cudaFuncAttributeMaxDynamicSharedMemorySize, G1_SMEM);
    }

    // fork: bucket build chain on side stream
    cudaEventRecord(ev_fork, 0);
    cudaStreamWaitEvent(s_csr, ev_fork, 0);
    init_kernel<<<NB, 256, 0, s_csr>>>(ei);
    fill_kernel<<<(E + 255) / 256, 256, 0, s_csr>>>(ei, E);
    dinv_kernel<<<NB, 256, 0, s_csr>>>();
    cudaEventRecord(ev_join, s_csr);

    // main stream: weights + GEMM1 (independent of edge structure)
    convert_w_kernel<<<(F_IN * H2 + 255) / 256, 256>>>(W1, W2);
    gemm1_pipe_kernel<<<NPAD / 128, 256, G1_SMEM>>>(x, p_m1, NN);

    // join: gather needs both GEMM1 output and edge buckets
    cudaStreamWaitEvent(0, ev_join, 0);
    gather_act_kernel<<<(NN * 32 + 255) / 256, 256>>>(p_m1, b1, p_m1a);

    // layer 2 + fused classifier
    gemm2_pipe_kernel<<<NPAD / 128, 256>>>(p_m1a, p_m2);
    gather_final_kernel<<<(NN + 7) / 8, 256>>>(p_m2, b2, Wl, bl, out);
}

// round 16
// speedup vs baseline: 1.1728x; 1.0076x over previous
#include <cstdint>
#include <cuda_runtime.h>
#include <cuda_fp16.h>
#include <cuda_bf16.h>
#include <math.h>

// Problem constants (fixed by the dataset)
#define NN      100000
#define NPAD    100096          // 782 * 128
#define NB      391             // (NN + 255) / 256
#define SLOTS   64              // per-node edge bucket (P(deg>=64) ~ 1e-20)
#define F_IN    256
#define H2      128
#define H1      64
#define NCLS    10

// ---------------------------------------------------------------------------
// Scratch (device globals; no runtime alloc)
// ---------------------------------------------------------------------------
__device__ int    g_cnt  [NPAD];
__device__ int    g_esrc [(size_t)NPAD * SLOTS];   // slot-bucketed sources
__device__ __half g_w1h  [F_IN * H2];              // W1 fp16
__device__ __half g_w2h  [H2 * H1];                // W2 fp16
__device__ __half g_m1h  [(size_t)NPAD * H2];      // x @ W1 (fp16)
__device__ __half g_m1act[(size_t)NPAD * H2];      // relu(agg1 + b1) (fp16)
__device__ __half g_m2h  [(size_t)NPAD * H1];      // m1act @ W2 (fp16)
__device__ int    g_is64;

// ---------------------------------------------------------------------------
// cp.async helpers
// ---------------------------------------------------------------------------
__device__ __forceinline__ void cp_async16(unsigned int dst, const void* src, int src_size) {
    asm volatile("cp.async.cg.shared.global [%0], [%1], 16, %2;\n"
                 :: "r"(dst), "l"(src), "r"(src_size));
}
__device__ __forceinline__ void cp_async16(unsigned int dst, const void* src) {
    asm volatile("cp.async.cg.shared.global [%0], [%1], 16;\n"
                 :: "r"(dst), "l"(src));
}
__device__ __forceinline__ void cp_commit() {
    asm volatile("cp.async.commit_group;\n");
}
__device__ __forceinline__ void cp_wait_all() {
    asm volatile("cp.async.wait_group 0;\n");
}
__device__ __forceinline__ void cp_wait_1() {
    asm volatile("cp.async.wait_group 1;\n");
}

// ---------------------------------------------------------------------------
// convert_init: W1/W2 fp32 -> fp16, zero g_cnt, detect edge_index dtype.
// grid = NB (100096 threads >= 32768 W1 elems, 100000 cnt slots)
// ---------------------------------------------------------------------------
__global__ void convert_init_kernel(const float* __restrict__ W1,
                                    const float* __restrict__ W2,
                                    const void* __restrict__ ei) {
    int i = blockIdx.x * blockDim.x + threadIdx.x;
    if (i < NN) g_cnt[i] = 0;
    if (i < F_IN * H2) g_w1h[i] = __float2half(W1[i]);
    if (i < H2 * H1)   g_w2h[i] = __float2half(W2[i]);
    if (blockIdx.x == 0) {
        __shared__ int snz;
        if (threadIdx.x == 0) snz = 0;
        __syncthreads();
        const int* p = (const int*)ei;
        int nz = 0;
        for (int k = threadIdx.x; k < 1024; k += blockDim.x) nz |= p[2 * k + 1];
        if (nz) atomicOr(&snz, 1);
        __syncthreads();
        if (threadIdx.x == 0) g_is64 = (snz == 0) ? 1 : 0;
    }
}

__device__ __forceinline__ int load_idx(const void* ei, long long pos) {
    if (g_is64) return (int)((const long long*)ei)[pos];
    return ((const int*)ei)[pos];
}

// ---------------------------------------------------------------------------
// single-pass bucket fill (cnt doubles as cursor and final degree)
// ---------------------------------------------------------------------------
__global__ void fill_kernel(const void* __restrict__ ei, int E) {
    int e = blockIdx.x * blockDim.x + threadIdx.x;
    if (e >= E) return;
    int s = load_idx(ei, e);
    int d = load_idx(ei, (long long)E + e);
    int pos = atomicAdd(&g_cnt[d], 1);
    if (pos < SLOTS) g_esrc[(size_t)d * SLOTS + pos] = s;
}

// ---------------------------------------------------------------------------
// mma helper
// ---------------------------------------------------------------------------
__device__ __forceinline__ void mma16816(float* c, const unsigned int* a,
                                         unsigned int b0, unsigned int b1) {
    asm volatile(
        "mma.sync.aligned.m16n8k16.row.col.f32.f16.f16.f32 "
        "{%0,%1,%2,%3}, {%4,%5,%6,%7}, {%8,%9}, {%0,%1,%2,%3};\n"
        : "+f"(c[0]), "+f"(c[1]), "+f"(c[2]), "+f"(c[3])
        : "r"(a[0]), "r"(a[1]), "r"(a[2]), "r"(a[3]), "r"(b0), "r"(b1));
}

__device__ __forceinline__ unsigned int packh2(float x, float y) {
    __half2 h = __floats2half2_rn(x, y);
    return *reinterpret_cast<unsigned int*>(&h);
}

// ---------------------------------------------------------------------------
// GEMM1 (3-stage pipeline): C[M,128](fp16) = A(fp32) @ W1h(fp16)
// cp.async: A staged fp32 -> smem convert pass -> fp16 ldmatrix layout.
// ---------------------------------------------------------------------------
#define G1_SMEM (49152 + 10240 + 26112)

__global__ __launch_bounds__(256, 2)
void gemm1_pipe_kernel(const float* __restrict__ A, __half* __restrict__ C, int M) {
    extern __shared__ __align__(16) char sm[];
    float*  As32 = reinterpret_cast<float*>(sm);              // [3][128][32]
    __half* As16 = reinterpret_cast<__half*>(sm + 49152);     // [128][40]
    __half* Bs   = reinterpret_cast<__half*>(sm + 59392);     // [3][32][136]

    const int tx    = threadIdx.x;
    const int lane  = tx & 31;
    const int warp  = tx >> 5;
    const int warpM = warp >> 1;
    const int warpN = warp & 1;
    const int row0  = blockIdx.x * 128;
    constexpr int NIT = F_IN / 32;            // 8

    float acc[2][8][4];
#pragma unroll
    for (int t = 0; t < 2; t++)
#pragma unroll
        for (int n = 0; n < 8; n++)
#pragma unroll
            for (int k = 0; k < 4; k++) acc[t][n][k] = 0.0f;

    auto load_stage = [&](int k0, int buf) {
#pragma unroll
        for (int l = 0; l < 4; ++l) {
            int idx = tx + l * 256;
            int r = idx >> 3, c = idx & 7;
            const float* src = A + (size_t)(row0 + r) * F_IN + k0 + c * 4;
            unsigned int dst = (unsigned int)__cvta_generic_to_shared(
                As32 + buf * 4096 + r * 32 + c * 4);
            cp_async16(dst, src, (row0 + r < M) ? 16 : 0);
        }
#pragma unroll
        for (int l = 0; l < 2; ++l) {
            int idx = tx + l * 256;
            int r = idx >> 4, c = idx & 15;
            const __half* src = g_w1h + (size_t)(k0 + r) * H2 + c * 8;
            unsigned int dst = (unsigned int)__cvta_generic_to_shared(
                Bs + buf * (32 * 136) + r * 136 + c * 8);
            cp_async16(dst, src);
        }
        cp_commit();
    };

    load_stage(0, 0);
    load_stage(32, 1);

#pragma unroll
    for (int it = 0; it < NIT; ++it) {
        int buf = it % 3;
        if (it == NIT - 1) cp_wait_all(); else cp_wait_1();
        __syncthreads();
        if (it + 2 < NIT) load_stage((it + 2) * 32, (it + 2) % 3);

        // convert As32[buf] -> As16 (padded [128][40])
#pragma unroll
        for (int l = 0; l < 4; ++l) {
            int idx = tx + l * 256;
            int r = idx >> 3, c = idx & 7;
            float4 v = *reinterpret_cast<const float4*>(As32 + buf * 4096 + r * 32 + c * 4);
            __half2* d = reinterpret_cast<__half2*>(As16 + r * 40 + c * 4);
            d[0] = __floats2half2_rn(v.x, v.y);
            d[1] = __floats2half2_rn(v.z, v.w);
        }
        __syncthreads();

#pragma unroll
        for (int p = 0; p < 2; ++p) {
            unsigned int a[2][4];
#pragma unroll
            for (int t = 0; t < 2; ++t) {
                const __half* ptr = As16 + (warpM * 32 + t * 16 + (lane & 15)) * 40
                                         + p * 16 + (lane >> 4) * 8;
                unsigned int sa = (unsigned int)__cvta_generic_to_shared(ptr);
                asm volatile("ldmatrix.sync.aligned.m8n8.x4.shared.b16 {%0,%1,%2,%3}, [%4];"
                             : "=r"(a[t][0]), "=r"(a[t][1]), "=r"(a[t][2]), "=r"(a[t][3])
                             : "r"(sa));
            }
            unsigned int b[8][2];
#pragma unroll
            for (int pr = 0; pr < 4; ++pr) {
                const __half* ptr = Bs + buf * (32 * 136)
                                       + (p * 16 + (lane & 15)) * 136
                                       + warpN * 64 + pr * 16 + (lane >> 4) * 8;
                unsigned int sa = (unsigned int)__cvta_generic_to_shared(ptr);
                unsigned int r0, r1, r2, r3;
                asm volatile("ldmatrix.sync.aligned.m8n8.x4.trans.shared.b16 {%0,%1,%2,%3}, [%4];"
                             : "=r"(r0), "=r"(r1), "=r"(r2), "=r"(r3)
                             : "r"(sa));
                b[pr * 2 + 0][0] = r0; b[pr * 2 + 0][1] = r1;
                b[pr * 2 + 1][0] = r2; b[pr * 2 + 1][1] = r3;
            }
#pragma unroll
            for (int t = 0; t < 2; ++t)
#pragma unroll
                for (int n = 0; n < 8; ++n)
                    mma16816(acc[t][n], a[t], b[n][0], b[n][1]);
        }
    }

#pragma unroll
    for (int t = 0; t < 2; ++t) {
        int r = row0 + warpM * 32 + t * 16 + (lane >> 2);
        int c0 = warpN * 64 + ((lane & 3) << 1);
#pragma unroll
        for (int n = 0; n < 8; ++n) {
            int c = c0 + n * 8;
            *reinterpret_cast<__half2*>(&C[(size_t)r * H2 + c]) =
                __floats2half2_rn(acc[t][n][0], acc[t][n][1]);
            *reinterpret_cast<__half2*>(&C[(size_t)(r + 8) * H2 + c]) =
                __floats2half2_rn(acc[t][n][2], acc[t][n][3]);
        }
    }
}

// ---------------------------------------------------------------------------
// GEMM2 (3-stage pipeline): C[M,64](fp16) = A[M,128](fp16) @ W2h(fp16)
// ---------------------------------------------------------------------------
__global__ __launch_bounds__(256, 2)
void gemm2_pipe_kernel(const __half* __restrict__ A, __half* __restrict__ C) {
    __shared__ __align__(16) __half As16[3][128][40];
    __shared__ __align__(16) __half Bs[3][32][72];

    const int tx    = threadIdx.x;
    const int lane  = tx & 31;
    const int warp  = tx >> 5;
    const int warpM = warp >> 1;
    const int warpN = warp & 1;
    const int row0  = blockIdx.x * 128;
    constexpr int NIT = H2 / 32;              // 4

    float acc[2][4][4];
#pragma unroll
    for (int t = 0; t < 2; t++)
#pragma unroll
        for (int n = 0; n < 4; n++)
#pragma unroll
            for (int k = 0; k < 4; k++) acc[t][n][k] = 0.0f;

    auto load_stage = [&](int k0, int buf) {
#pragma unroll
        for (int l = 0; l < 2; ++l) {
            int idx = tx + l * 256;
            int r = idx >> 2, c = idx & 3;
            const __half* src = A + (size_t)(row0 + r) * H2 + k0 + c * 8;
            unsigned int dst = (unsigned int)__cvta_generic_to_shared(
                &As16[buf][r][c * 8]);
            cp_async16(dst, src);
        }
        {
            int r = tx >> 3, c = tx & 7;
            const __half* src = g_w2h + (size_t)(k0 + r) * H1 + c * 8;
            unsigned int dst = (unsigned int)__cvta_generic_to_shared(
                &Bs[buf][r][c * 8]);
            cp_async16(dst, src);
        }
        cp_commit();
    };

    load_stage(0, 0);
    load_stage(32, 1);

#pragma unroll
    for (int it = 0; it < NIT; ++it) {
        int buf = it % 3;
        if (it == NIT - 1) cp_wait_all(); else cp_wait_1();
        __syncthreads();                      // also protects buf reuse (3-stage)
        if (it + 2 < NIT) load_stage((it + 2) * 32, (it + 2) % 3);

#pragma unroll
        for (int p = 0; p < 2; ++p) {
            unsigned int a[2][4];
#pragma unroll
            for (int t = 0; t < 2; ++t) {
                const __half* ptr = &As16[buf][warpM * 32 + t * 16 + (lane & 15)][p * 16 + (lane >> 4) * 8];
                unsigned int sa = (unsigned int)__cvta_generic_to_shared(ptr);
                asm volatile("ldmatrix.sync.aligned.m8n8.x4.shared.b16 {%0,%1,%2,%3}, [%4];"
                             : "=r"(a[t][0]), "=r"(a[t][1]), "=r"(a[t][2]), "=r"(a[t][3])
                             : "r"(sa));
            }
            unsigned int b[4][2];
#pragma unroll
            for (int pr = 0; pr < 2; ++pr) {
                const __half* ptr = &Bs[buf][p * 16 + (lane & 15)][warpN * 32 + pr * 16 + (lane >> 4) * 8];
                unsigned int sa = (unsigned int)__cvta_generic_to_shared(ptr);
                unsigned int r0, r1, r2, r3;
                asm volatile("ldmatrix.sync.aligned.m8n8.x4.trans.shared.b16 {%0,%1,%2,%3}, [%4];"
                             : "=r"(r0), "=r"(r1), "=r"(r2), "=r"(r3)
                             : "r"(sa));
                b[pr * 2 + 0][0] = r0; b[pr * 2 + 0][1] = r1;
                b[pr * 2 + 1][0] = r2; b[pr * 2 + 1][1] = r3;
            }
#pragma unroll
            for (int t = 0; t < 2; ++t)
#pragma unroll
                for (int n = 0; n < 4; ++n)
                    mma16816(acc[t][n], a[t], b[n][0], b[n][1]);
        }
    }

#pragma unroll
    for (int t = 0; t < 2; ++t) {
        int r = row0 + warpM * 32 + t * 16 + (lane >> 2);
        int c0 = warpN * 32 + ((lane & 3) << 1);
#pragma unroll
        for (int n = 0; n < 4; ++n) {
            int c = c0 + n * 8;
            *reinterpret_cast<__half2*>(&C[(size_t)r * H1 + c]) =
                __floats2half2_rn(acc[t][n][0], acc[t][n][1]);
            *reinterpret_cast<__half2*>(&C[(size_t)(r + 8) * H1 + c]) =
                __floats2half2_rn(acc[t][n][2], acc[t][n][3]);
        }
    }
}

// ---------------------------------------------------------------------------
// helpers
// ---------------------------------------------------------------------------
__device__ __forceinline__ float2 h2f(unsigned int u) {
    __half2 h = *reinterpret_cast<__half2*>(&u);
    return __half22float2(h);
}

__device__ __forceinline__ float dinv_of(int node) {
    return rsqrtf((float)(g_cnt[node] + 1));   // +1 self loop
}

// ---------------------------------------------------------------------------
// gather1 + bias + relu + fp16 cast: warp per node, F=128, uint2 loads,
// unroll x4 (measured-optimal). dinv computed inline from g_cnt.
// ---------------------------------------------------------------------------
__global__ void gather_act_kernel(const __half* __restrict__ m,
                                  const float* __restrict__ bias,
                                  __half* __restrict__ mact) {
    int gw = (blockIdx.x * blockDim.x + threadIdx.x) >> 5;
    if (gw >= NN) return;
    int lane = threadIdx.x & 31;

    int cfull = g_cnt[gw];
    float di = rsqrtf((float)(cfull + 1));
    float wself = di * di;
    int cnt = min(cfull, SLOTS);
    const size_t base = (size_t)gw * SLOTS;

    uint2 rw = *reinterpret_cast<const uint2*>(m + (size_t)gw * H2 + lane * 4);
    float2 f0 = h2f(rw.x), f1 = h2f(rw.y);
    float4 acc = make_float4(f0.x * wself, f0.y * wself, f1.x * wself, f1.y * wself);

    for (int j0 = 0; j0 < cnt; j0 += 32) {
        int n = min(32, cnt - j0);
        int s = 0; float w = 0.f;
        if (lane < n) {
            s = g_esrc[base + j0 + lane];
            w = dinv_of(s) * di;
        }
        int t = 0;
        for (; t + 4 <= n; t += 4) {
            int   s0 = __shfl_sync(0xffffffffu, s, t);
            int   s1 = __shfl_sync(0xffffffffu, s, t + 1);
            int   s2 = __shfl_sync(0xffffffffu, s, t + 2);
            int   s3 = __shfl_sync(0xffffffffu, s, t + 3);
            float w0 = __shfl_sync(0xffffffffu, w, t);
            float w1 = __shfl_sync(0xffffffffu, w, t + 1);
            float w2 = __shfl_sync(0xffffffffu, w, t + 2);
            float w3 = __shfl_sync(0xffffffffu, w, t + 3);
            uint2 u0 = *reinterpret_cast<const uint2*>(m + (size_t)s0 * H2 + lane * 4);
            uint2 u1 = *reinterpret_cast<const uint2*>(m + (size_t)s1 * H2 + lane * 4);
            uint2 u2 = *reinterpret_cast<const uint2*>(m + (size_t)s2 * H2 + lane * 4);
            uint2 u3 = *reinterpret_cast<const uint2*>(m + (size_t)s3 * H2 + lane * 4);
            float2 a0, a1;
            a0 = h2f(u0.x); a1 = h2f(u0.y);
            acc.x += a0.x * w0; acc.y += a0.y * w0; acc.z += a1.x * w0; acc.w += a1.y * w0;
            a0 = h2f(u1.x); a1 = h2f(u1.y);
            acc.x += a0.x * w1; acc.y += a0.y * w1; acc.z += a1.x * w1; acc.w += a1.y * w1;
            a0 = h2f(u2.x); a1 = h2f(u2.y);
            acc.x += a0.x * w2; acc.y += a0.y * w2; acc.z += a1.x * w2; acc.w += a1.y * w2;
            a0 = h2f(u3.x); a1 = h2f(u3.y);
            acc.x += a0.x * w3; acc.y += a0.y * w3; acc.z += a1.x * w3; acc.w += a1.y * w3;
        }
        for (; t < n; ++t) {
            int   st = __shfl_sync(0xffffffffu, s, t);
            float wt = __shfl_sync(0xffffffffu, w, t);
            uint2 u = *reinterpret_cast<const uint2*>(m + (size_t)st * H2 + lane * 4);
            float2 a0 = h2f(u.x), a1 = h2f(u.y);
            acc.x += a0.x * wt; acc.y += a0.y * wt;
            acc.z += a1.x * wt; acc.w += a1.y * wt;
        }
    }

    float4 bb = *reinterpret_cast<const float4*>(&bias[lane * 4]);
    acc.x = fmaxf(acc.x + bb.x, 0.f);
    acc.y = fmaxf(acc.y + bb.y, 0.f);
    acc.z = fmaxf(acc.z + bb.z, 0.f);
    acc.w = fmaxf(acc.w + bb.w, 0.f);
    uint2 outw;
    outw.x = packh2(acc.x, acc.y);
    outw.y = packh2(acc.z, acc.w);
    *reinterpret_cast<uint2*>(mact + (size_t)gw * H2 + lane * 4) = outw;
}

// ---------------------------------------------------------------------------
// gather2 + classifier + log_softmax fused: warp per node, F=64,
// per-edge broadcast, uint32 loads, unroll x4 (measured-optimal).
// ---------------------------------------------------------------------------
__global__ void gather_final_kernel(const __half* __restrict__ m,
                                    const float* __restrict__ b2,
                                    const float* __restrict__ Wl,
                                    const float* __restrict__ bl,
                                    float* __restrict__ out) {
    __shared__ float sW[H1 * NCLS];
    __shared__ float sb[NCLS];
    for (int i = threadIdx.x; i < H1 * NCLS; i += blockDim.x) sW[i] = Wl[i];
    if (threadIdx.x < NCLS) sb[threadIdx.x] = bl[threadIdx.x];
    __syncthreads();

    int gw = (blockIdx.x * blockDim.x + threadIdx.x) >> 5;
    if (gw >= NN) return;
    int lane = threadIdx.x & 31;

    int cfull = g_cnt[gw];
    float di = rsqrtf((float)(cfull + 1));
    float wself = di * di;
    int cnt = min(cfull, SLOTS);
    const size_t base = (size_t)gw * SLOTS;

    unsigned int rw = *reinterpret_cast<const unsigned int*>(m + (size_t)gw * H1 + lane * 2);
    float2 f = h2f(rw);
    float2 acc = make_float2(f.x * wself, f.y * wself);

    for (int j0 = 0; j0 < cnt; j0 += 32) {
        int n = min(32, cnt - j0);
        int s = 0; float w = 0.f;
        if (lane < n) {
            s = g_esrc[base + j0 + lane];
            w = dinv_of(s) * di;
        }
        int t = 0;
        for (; t + 4 <= n; t += 4) {
            int   s0 = __shfl_sync(0xffffffffu, s, t);
            int   s1 = __shfl_sync(0xffffffffu, s, t + 1);
            int   s2 = __shfl_sync(0xffffffffu, s, t + 2);
            int   s3 = __shfl_sync(0xffffffffu, s, t + 3);
            float w0 = __shfl_sync(0xffffffffu, w, t);
            float w1 = __shfl_sync(0xffffffffu, w, t + 1);
            float w2 = __shfl_sync(0xffffffffu, w, t + 2);
            float w3 = __shfl_sync(0xffffffffu, w, t + 3);
            unsigned int u0 = *reinterpret_cast<const unsigned int*>(m + (size_t)s0 * H1 + lane * 2);
            unsigned int u1 = *reinterpret_cast<const unsigned int*>(m + (size_t)s1 * H1 + lane * 2);
            unsigned int u2 = *reinterpret_cast<const unsigned int*>(m + (size_t)s2 * H1 + lane * 2);
            unsigned int u3 = *reinterpret_cast<const unsigned int*>(m + (size_t)s3 * H1 + lane * 2);
            float2 a0;
            a0 = h2f(u0); acc.x += a0.x * w0; acc.y += a0.y * w0;
            a0 = h2f(u1); acc.x += a0.x * w1; acc.y += a0.y * w1;
            a0 = h2f(u2); acc.x += a0.x * w2; acc.y += a0.y * w2;
            a0 = h2f(u3); acc.x += a0.x * w3; acc.y += a0.y * w3;
        }
        for (; t < n; ++t) {
            int   st = __shfl_sync(0xffffffffu, s, t);
            float wt = __shfl_sync(0xffffffffu, w, t);
            unsigned int u = *reinterpret_cast<const unsigned int*>(m + (size_t)st * H1 + lane * 2);
            float2 a0 = h2f(u);
            acc.x += a0.x * wt; acc.y += a0.y * wt;
        }
    }

    float2 bb = *reinterpret_cast<const float2*>(&b2[lane * 2]);
    float h0 = fmaxf(acc.x + bb.x, 0.f);
    float h1 = fmaxf(acc.y + bb.y, 0.f);

    float logit[NCLS];
#pragma unroll
    for (int c = 0; c < NCLS; c++) {
        float p = h0 * sW[(lane * 2) * NCLS + c] + h1 * sW[(lane * 2 + 1) * NCLS + c];
#pragma unroll
        for (int o = 16; o; o >>= 1) p += __shfl_xor_sync(0xffffffffu, p, o);
        logit[c] = p + sb[c];
    }
    float mx = logit[0];
#pragma unroll
    for (int c = 1; c < NCLS; c++) mx = fmaxf(mx, logit[c]);
    float se = 0.f;
#pragma unroll
    for (int c = 0; c < NCLS; c++) se += expf(logit[c] - mx);
    float lse = mx + logf(se);
    if (lane < NCLS) out[(size_t)gw * NCLS + lane] = logit[lane] - lse;
}

// ---------------------------------------------------------------------------
// Launcher: convert_init(1) -> gemm1(2) on main; fill(3) on side stream
// (waits on convert_init); gather_act(4) [profiled slot], gemm2(5),
// gather_final(6).
// ---------------------------------------------------------------------------
extern "C" void kernel_launch(void* const* d_in, const int* in_sizes, int n_in,
                              void* d_out, int out_size) {
    const float* x  = (const float*)d_in[0];
    const void*  ei = d_in[1];
    const float* W1 = (const float*)d_in[2];
    const float* b1 = (const float*)d_in[3];
    const float* W2 = (const float*)d_in[4];
    const float* b2 = (const float*)d_in[5];
    const float* Wl = (const float*)d_in[6];
    const float* bl = (const float*)d_in[7];
    float* out = (float*)d_out;
    const int E = in_sizes[1] / 2;

    __half* p_m1  = nullptr; cudaGetSymbolAddress((void**)&p_m1,  g_m1h);
    __half* p_m1a = nullptr; cudaGetSymbolAddress((void**)&p_m1a, g_m1act);
    __half* p_m2  = nullptr; cudaGetSymbolAddress((void**)&p_m2,  g_m2h);

    static cudaStream_t s_csr = nullptr;
    static cudaEvent_t  ev_fork = nullptr, ev_join = nullptr;
    if (s_csr == nullptr) {
        cudaStreamCreateWithFlags(&s_csr, cudaStreamNonBlocking);
        cudaEventCreateWithFlags(&ev_fork, cudaEventDisableTiming);
        cudaEventCreateWithFlags(&ev_join, cudaEventDisableTiming);
        cudaFuncSetAttribute(gemm1_pipe_kernel,
                             cudaFuncAttributeMaxDynamicSharedMemorySize, G1_SMEM);
    }

    // (1) convert weights + zero counters + detect dtype
    convert_init_kernel<<<NB, 256>>>(W1, W2, ei);
    cudaEventRecord(ev_fork, 0);               // fill needs zeroed counters

    // (2) GEMM1 on main stream (needs w1h from convert_init, same stream)
    gemm1_pipe_kernel<<<NPAD / 128, 256, G1_SMEM>>>(x, p_m1, NN);

    // (3) bucket fill on side stream, overlapped with GEMM1
    cudaStreamWaitEvent(s_csr, ev_fork, 0);
    fill_kernel<<<(E + 255) / 256, 256, 0, s_csr>>>(ei, E);
    cudaEventRecord(ev_join, s_csr);

    // join: gather needs both GEMM1 output and edge buckets
    cudaStreamWaitEvent(0, ev_join, 0);

    // (4) gather1 + bias + relu  [ncu-profiled slot]
    gather_act_kernel<<<(NN * 32 + 255) / 256, 256>>>(p_m1, b1, p_m1a);

    // (5) GEMM2, (6) gather2 + classifier + log_softmax
    gemm2_pipe_kernel<<<NPAD / 128, 256>>>(p_m1a, p_m2);
    gather_final_kernel<<<(NN + 7) / 8, 256>>>(p_m2, b2, Wl, bl, out);
}

// round 17
// speedup vs baseline: 1.1743x; 1.0012x over previous
#include <cstdint>
#include <cuda_runtime.h>
#include <cuda_fp16.h>
#include <cuda_bf16.h>
#include <math.h>

// Problem constants (fixed by the dataset)
#define NN      100000
#define NPAD    100096          // 782 * 128
#define NB      391             // (NN + 255) / 256
#define SLOTS   64              // per-node edge bucket (P(deg>=64) ~ 1e-20)
#define F_IN    256
#define H2      128
#define H1      64
#define NCLS    10

// ---------------------------------------------------------------------------
// Scratch (device globals; no runtime alloc)
// ---------------------------------------------------------------------------
__device__ int    g_cnt  [NPAD];
__device__ int    g_esrc [(size_t)NPAD * SLOTS];   // slot-bucketed sources
__device__ __half g_w1h  [F_IN * H2];              // W1 fp16
__device__ __half g_w2h  [H2 * H1];                // W2 fp16
__device__ __half g_m1h  [(size_t)NPAD * H2];      // x @ W1 (fp16)
__device__ __half g_m1act[(size_t)NPAD * H2];      // relu(agg1 + b1) (fp16)
__device__ __half g_m2h  [(size_t)NPAD * H1];      // m1act @ W2 (fp16)
__device__ int    g_is64;

// ---------------------------------------------------------------------------
// cp.async helpers
// ---------------------------------------------------------------------------
__device__ __forceinline__ void cp_async16(unsigned int dst, const void* src, int src_size) {
    asm volatile("cp.async.cg.shared.global [%0], [%1], 16, %2;\n"
                 :: "r"(dst), "l"(src), "r"(src_size));
}
__device__ __forceinline__ void cp_async16(unsigned int dst, const void* src) {
    asm volatile("cp.async.cg.shared.global [%0], [%1], 16;\n"
                 :: "r"(dst), "l"(src));
}
__device__ __forceinline__ void cp_commit() {
    asm volatile("cp.async.commit_group;\n");
}
__device__ __forceinline__ void cp_wait_all() {
    asm volatile("cp.async.wait_group 0;\n");
}
__device__ __forceinline__ void cp_wait_1() {
    asm volatile("cp.async.wait_group 1;\n");
}

// ---------------------------------------------------------------------------
// convert_init: W1/W2 fp32 -> fp16, zero g_cnt, detect edge_index dtype.
// ---------------------------------------------------------------------------
__global__ void convert_init_kernel(const float* __restrict__ W1,
                                    const float* __restrict__ W2,
                                    const void* __restrict__ ei) {
    int i = blockIdx.x * blockDim.x + threadIdx.x;
    if (i < NN) g_cnt[i] = 0;
    if (i < F_IN * H2) g_w1h[i] = __float2half(W1[i]);
    if (i < H2 * H1)   g_w2h[i] = __float2half(W2[i]);
    if (blockIdx.x == 0) {
        __shared__ int snz;
        if (threadIdx.x == 0) snz = 0;
        __syncthreads();
        const int* p = (const int*)ei;
        int nz = 0;
        for (int k = threadIdx.x; k < 1024; k += blockDim.x) nz |= p[2 * k + 1];
        if (nz) atomicOr(&snz, 1);
        __syncthreads();
        if (threadIdx.x == 0) g_is64 = (snz == 0) ? 1 : 0;
    }
}

__device__ __forceinline__ int load_idx(const void* ei, long long pos) {
    if (g_is64) return (int)((const long long*)ei)[pos];
    return ((const int*)ei)[pos];
}

// ---------------------------------------------------------------------------
// single-pass bucket fill (cnt doubles as cursor and final degree)
// ---------------------------------------------------------------------------
__global__ void fill_kernel(const void* __restrict__ ei, int E) {
    int e = blockIdx.x * blockDim.x + threadIdx.x;
    if (e >= E) return;
    int s = load_idx(ei, e);
    int d = load_idx(ei, (long long)E + e);
    int pos = atomicAdd(&g_cnt[d], 1);
    if (pos < SLOTS) g_esrc[(size_t)d * SLOTS + pos] = s;
}

// ---------------------------------------------------------------------------
// mma helper
// ---------------------------------------------------------------------------
__device__ __forceinline__ void mma16816(float* c, const unsigned int* a,
                                         unsigned int b0, unsigned int b1) {
    asm volatile(
        "mma.sync.aligned.m16n8k16.row.col.f32.f16.f16.f32 "
        "{%0,%1,%2,%3}, {%4,%5,%6,%7}, {%8,%9}, {%0,%1,%2,%3};\n"
        : "+f"(c[0]), "+f"(c[1]), "+f"(c[2]), "+f"(c[3])
        : "r"(a[0]), "r"(a[1]), "r"(a[2]), "r"(a[3]), "r"(b0), "r"(b1));
}

__device__ __forceinline__ unsigned int packh2(float x, float y) {
    __half2 h = __floats2half2_rn(x, y);
    return *reinterpret_cast<unsigned int*>(&h);
}

__device__ __forceinline__ __half2 u2h2(unsigned int u) {
    return *reinterpret_cast<__half2*>(&u);
}

// ---------------------------------------------------------------------------
// GEMM1 (3-stage pipeline): C[M,128](fp16) = A(fp32) @ W1h(fp16)
// ---------------------------------------------------------------------------
#define G1_SMEM (49152 + 10240 + 26112)

__global__ __launch_bounds__(256, 2)
void gemm1_pipe_kernel(const float* __restrict__ A, __half* __restrict__ C, int M) {
    extern __shared__ __align__(16) char sm[];
    float*  As32 = reinterpret_cast<float*>(sm);              // [3][128][32]
    __half* As16 = reinterpret_cast<__half*>(sm + 49152);     // [128][40]
    __half* Bs   = reinterpret_cast<__half*>(sm + 59392);     // [3][32][136]

    const int tx    = threadIdx.x;
    const int lane  = tx & 31;
    const int warp  = tx >> 5;
    const int warpM = warp >> 1;
    const int warpN = warp & 1;
    const int row0  = blockIdx.x * 128;
    constexpr int NIT = F_IN / 32;            // 8

    float acc[2][8][4];
#pragma unroll
    for (int t = 0; t < 2; t++)
#pragma unroll
        for (int n = 0; n < 8; n++)
#pragma unroll
            for (int k = 0; k < 4; k++) acc[t][n][k] = 0.0f;

    auto load_stage = [&](int k0, int buf) {
#pragma unroll
        for (int l = 0; l < 4; ++l) {
            int idx = tx + l * 256;
            int r = idx >> 3, c = idx & 7;
            const float* src = A + (size_t)(row0 + r) * F_IN + k0 + c * 4;
            unsigned int dst = (unsigned int)__cvta_generic_to_shared(
                As32 + buf * 4096 + r * 32 + c * 4);
            cp_async16(dst, src, (row0 + r < M) ? 16 : 0);
        }
#pragma unroll
        for (int l = 0; l < 2; ++l) {
            int idx = tx + l * 256;
            int r = idx >> 4, c = idx & 15;
            const __half* src = g_w1h + (size_t)(k0 + r) * H2 + c * 8;
            unsigned int dst = (unsigned int)__cvta_generic_to_shared(
                Bs + buf * (32 * 136) + r * 136 + c * 8);
            cp_async16(dst, src);
        }
        cp_commit();
    };

    load_stage(0, 0);
    load_stage(32, 1);

#pragma unroll
    for (int it = 0; it < NIT; ++it) {
        int buf = it % 3;
        if (it == NIT - 1) cp_wait_all(); else cp_wait_1();
        __syncthreads();
        if (it + 2 < NIT) load_stage((it + 2) * 32, (it + 2) % 3);

        // convert As32[buf] -> As16 (padded [128][40])
#pragma unroll
        for (int l = 0; l < 4; ++l) {
            int idx = tx + l * 256;
            int r = idx >> 3, c = idx & 7;
            float4 v = *reinterpret_cast<const float4*>(As32 + buf * 4096 + r * 32 + c * 4);
            __half2* d = reinterpret_cast<__half2*>(As16 + r * 40 + c * 4);
            d[0] = __floats2half2_rn(v.x, v.y);
            d[1] = __floats2half2_rn(v.z, v.w);
        }
        __syncthreads();

#pragma unroll
        for (int p = 0; p < 2; ++p) {
            unsigned int a[2][4];
#pragma unroll
            for (int t = 0; t < 2; ++t) {
                const __half* ptr = As16 + (warpM * 32 + t * 16 + (lane & 15)) * 40
                                         + p * 16 + (lane >> 4) * 8;
                unsigned int sa = (unsigned int)__cvta_generic_to_shared(ptr);
                asm volatile("ldmatrix.sync.aligned.m8n8.x4.shared.b16 {%0,%1,%2,%3}, [%4];"
                             : "=r"(a[t][0]), "=r"(a[t][1]), "=r"(a[t][2]), "=r"(a[t][3])
                             : "r"(sa));
            }
            unsigned int b[8][2];
#pragma unroll
            for (int pr = 0; pr < 4; ++pr) {
                const __half* ptr = Bs + buf * (32 * 136)
                                       + (p * 16 + (lane & 15)) * 136
                                       + warpN * 64 + pr * 16 + (lane >> 4) * 8;
                unsigned int sa = (unsigned int)__cvta_generic_to_shared(ptr);
                unsigned int r0, r1, r2, r3;
                asm volatile("ldmatrix.sync.aligned.m8n8.x4.trans.shared.b16 {%0,%1,%2,%3}, [%4];"
                             : "=r"(r0), "=r"(r1), "=r"(r2), "=r"(r3)
                             : "r"(sa));
                b[pr * 2 + 0][0] = r0; b[pr * 2 + 0][1] = r1;
                b[pr * 2 + 1][0] = r2; b[pr * 2 + 1][1] = r3;
            }
#pragma unroll
            for (int t = 0; t < 2; ++t)
#pragma unroll
                for (int n = 0; n < 8; ++n)
                    mma16816(acc[t][n], a[t], b[n][0], b[n][1]);
        }
    }

#pragma unroll
    for (int t = 0; t < 2; ++t) {
        int r = row0 + warpM * 32 + t * 16 + (lane >> 2);
        int c0 = warpN * 64 + ((lane & 3) << 1);
#pragma unroll
        for (int n = 0; n < 8; ++n) {
            int c = c0 + n * 8;
            *reinterpret_cast<__half2*>(&C[(size_t)r * H2 + c]) =
                __floats2half2_rn(acc[t][n][0], acc[t][n][1]);
            *reinterpret_cast<__half2*>(&C[(size_t)(r + 8) * H2 + c]) =
                __floats2half2_rn(acc[t][n][2], acc[t][n][3]);
        }
    }
}

// ---------------------------------------------------------------------------
// GEMM2 (3-stage pipeline): C[M,64](fp16) = A[M,128](fp16) @ W2h(fp16)
// ---------------------------------------------------------------------------
__global__ __launch_bounds__(256, 2)
void gemm2_pipe_kernel(const __half* __restrict__ A, __half* __restrict__ C) {
    __shared__ __align__(16) __half As16[3][128][40];
    __shared__ __align__(16) __half Bs[3][32][72];

    const int tx    = threadIdx.x;
    const int lane  = tx & 31;
    const int warp  = tx >> 5;
    const int warpM = warp >> 1;
    const int warpN = warp & 1;
    const int row0  = blockIdx.x * 128;
    constexpr int NIT = H2 / 32;              // 4

    float acc[2][4][4];
#pragma unroll
    for (int t = 0; t < 2; t++)
#pragma unroll
        for (int n = 0; n < 4; n++)
#pragma unroll
            for (int k = 0; k < 4; k++) acc[t][n][k] = 0.0f;

    auto load_stage = [&](int k0, int buf) {
#pragma unroll
        for (int l = 0; l < 2; ++l) {
            int idx = tx + l * 256;
            int r = idx >> 2, c = idx & 3;
            const __half* src = A + (size_t)(row0 + r) * H2 + k0 + c * 8;
            unsigned int dst = (unsigned int)__cvta_generic_to_shared(
                &As16[buf][r][c * 8]);
            cp_async16(dst, src);
        }
        {
            int r = tx >> 3, c = tx & 7;
            const __half* src = g_w2h + (size_t)(k0 + r) * H1 + c * 8;
            unsigned int dst = (unsigned int)__cvta_generic_to_shared(
                &Bs[buf][r][c * 8]);
            cp_async16(dst, src);
        }
        cp_commit();
    };

    load_stage(0, 0);
    load_stage(32, 1);

#pragma unroll
    for (int it = 0; it < NIT; ++it) {
        int buf = it % 3;
        if (it == NIT - 1) cp_wait_all(); else cp_wait_1();
        __syncthreads();                      // also protects buf reuse (3-stage)
        if (it + 2 < NIT) load_stage((it + 2) * 32, (it + 2) % 3);

#pragma unroll
        for (int p = 0; p < 2; ++p) {
            unsigned int a[2][4];
#pragma unroll
            for (int t = 0; t < 2; ++t) {
                const __half* ptr = &As16[buf][warpM * 32 + t * 16 + (lane & 15)][p * 16 + (lane >> 4) * 8];
                unsigned int sa = (unsigned int)__cvta_generic_to_shared(ptr);
                asm volatile("ldmatrix.sync.aligned.m8n8.x4.shared.b16 {%0,%1,%2,%3}, [%4];"
                             : "=r"(a[t][0]), "=r"(a[t][1]), "=r"(a[t][2]), "=r"(a[t][3])
                             : "r"(sa));
            }
            unsigned int b[4][2];
#pragma unroll
            for (int pr = 0; pr < 2; ++pr) {
                const __half* ptr = &Bs[buf][p * 16 + (lane & 15)][warpN * 32 + pr * 16 + (lane >> 4) * 8];
                unsigned int sa = (unsigned int)__cvta_generic_to_shared(ptr);
                unsigned int r0, r1, r2, r3;
                asm volatile("ldmatrix.sync.aligned.m8n8.x4.trans.shared.b16 {%0,%1,%2,%3}, [%4];"
                             : "=r"(r0), "=r"(r1), "=r"(r2), "=r"(r3)
                             : "r"(sa));
                b[pr * 2 + 0][0] = r0; b[pr * 2 + 0][1] = r1;
                b[pr * 2 + 1][0] = r2; b[pr * 2 + 1][1] = r3;
            }
#pragma unroll
            for (int t = 0; t < 2; ++t)
#pragma unroll
                for (int n = 0; n < 4; ++n)
                    mma16816(acc[t][n], a[t], b[n][0], b[n][1]);
        }
    }

#pragma unroll
    for (int t = 0; t < 2; ++t) {
        int r = row0 + warpM * 32 + t * 16 + (lane >> 2);
        int c0 = warpN * 32 + ((lane & 3) << 1);
#pragma unroll
        for (int n = 0; n < 4; ++n) {
            int c = c0 + n * 8;
            *reinterpret_cast<__half2*>(&C[(size_t)r * H1 + c]) =
                __floats2half2_rn(acc[t][n][0], acc[t][n][1]);
            *reinterpret_cast<__half2*>(&C[(size_t)(r + 8) * H1 + c]) =
                __floats2half2_rn(acc[t][n][2], acc[t][n][3]);
        }
    }
}

// ---------------------------------------------------------------------------
// helpers
// ---------------------------------------------------------------------------
__device__ __forceinline__ float2 h2f(unsigned int u) {
    __half2 h = *reinterpret_cast<__half2*>(&u);
    return __half22float2(h);
}

__device__ __forceinline__ float dinv_of(int node) {
    return rsqrtf((float)(g_cnt[node] + 1));   // +1 self loop
}

// ---------------------------------------------------------------------------
// gather1 + bias + relu + fp16 cast: warp per node, F=128.
// Packed HFMA2 accumulation over 4-edge chains, flushed to fp32 each chain.
// Staging lane pre-splats the edge weight to half2; shfl carries half2 bits.
// ---------------------------------------------------------------------------
__global__ void gather_act_kernel(const __half* __restrict__ m,
                                  const float* __restrict__ bias,
                                  __half* __restrict__ mact) {
    int gw = (blockIdx.x * blockDim.x + threadIdx.x) >> 5;
    if (gw >= NN) return;
    int lane = threadIdx.x & 31;

    int cfull = g_cnt[gw];
    float di = rsqrtf((float)(cfull + 1));
    float wself = di * di;
    int cnt = min(cfull, SLOTS);
    const size_t base = (size_t)gw * SLOTS;

    uint2 rw = *reinterpret_cast<const uint2*>(m + (size_t)gw * H2 + lane * 4);
    float2 f0 = h2f(rw.x), f1 = h2f(rw.y);
    float4 acc = make_float4(f0.x * wself, f0.y * wself, f1.x * wself, f1.y * wself);

    for (int j0 = 0; j0 < cnt; j0 += 32) {
        int n = min(32, cnt - j0);
        int s = 0; unsigned int wh = 0; float w = 0.f;
        if (lane < n) {
            s = g_esrc[base + j0 + lane];
            w = dinv_of(s) * di;
            wh = packh2(w, w);                 // half2 splat of weight
        }
        int t = 0;
        for (; t + 4 <= n; t += 4) {
            int s0 = __shfl_sync(0xffffffffu, s, t);
            int s1 = __shfl_sync(0xffffffffu, s, t + 1);
            int s2 = __shfl_sync(0xffffffffu, s, t + 2);
            int s3 = __shfl_sync(0xffffffffu, s, t + 3);
            unsigned int w0 = __shfl_sync(0xffffffffu, wh, t);
            unsigned int w1 = __shfl_sync(0xffffffffu, wh, t + 1);
            unsigned int w2 = __shfl_sync(0xffffffffu, wh, t + 2);
            unsigned int w3 = __shfl_sync(0xffffffffu, wh, t + 3);
            uint2 u0 = *reinterpret_cast<const uint2*>(m + (size_t)s0 * H2 + lane * 4);
            uint2 u1 = *reinterpret_cast<const uint2*>(m + (size_t)s1 * H2 + lane * 4);
            uint2 u2 = *reinterpret_cast<const uint2*>(m + (size_t)s2 * H2 + lane * 4);
            uint2 u3 = *reinterpret_cast<const uint2*>(m + (size_t)s3 * H2 + lane * 4);
            // 4-term fp16 chains, then flush to fp32
            __half2 p0 = __hmul2(u2h2(u0.x), u2h2(w0));
            __half2 p1 = __hmul2(u2h2(u0.y), u2h2(w0));
            p0 = __hfma2(u2h2(u1.x), u2h2(w1), p0);
            p1 = __hfma2(u2h2(u1.y), u2h2(w1), p1);
            p0 = __hfma2(u2h2(u2.x), u2h2(w2), p0);
            p1 = __hfma2(u2h2(u2.y), u2h2(w2), p1);
            p0 = __hfma2(u2h2(u3.x), u2h2(w3), p0);
            p1 = __hfma2(u2h2(u3.y), u2h2(w3), p1);
            float2 q0 = __half22float2(p0), q1 = __half22float2(p1);
            acc.x += q0.x; acc.y += q0.y; acc.z += q1.x; acc.w += q1.y;
        }
        for (; t < n; ++t) {
            int   st = __shfl_sync(0xffffffffu, s, t);
            float wt = __shfl_sync(0xffffffffu, w, t);
            uint2 u = *reinterpret_cast<const uint2*>(m + (size_t)st * H2 + lane * 4);
            float2 a0 = h2f(u.x), a1 = h2f(u.y);
            acc.x += a0.x * wt; acc.y += a0.y * wt;
            acc.z += a1.x * wt; acc.w += a1.y * wt;
        }
    }

    float4 bb = *reinterpret_cast<const float4*>(&bias[lane * 4]);
    acc.x = fmaxf(acc.x + bb.x, 0.f);
    acc.y = fmaxf(acc.y + bb.y, 0.f);
    acc.z = fmaxf(acc.z + bb.z, 0.f);
    acc.w = fmaxf(acc.w + bb.w, 0.f);
    uint2 outw;
    outw.x = packh2(acc.x, acc.y);
    outw.y = packh2(acc.z, acc.w);
    *reinterpret_cast<uint2*>(mact + (size_t)gw * H2 + lane * 4) = outw;
}

// ---------------------------------------------------------------------------
// gather2 + classifier + log_softmax fused: warp per node, F=64.
// Packed HFMA2 accumulation (4-edge chains, fp32 flush).
// ---------------------------------------------------------------------------
__global__ void gather_final_kernel(const __half* __restrict__ m,
                                    const float* __restrict__ b2,
                                    const float* __restrict__ Wl,
                                    const float* __restrict__ bl,
                                    float* __restrict__ out) {
    __shared__ float sW[H1 * NCLS];
    __shared__ float sb[NCLS];
    for (int i = threadIdx.x; i < H1 * NCLS; i += blockDim.x) sW[i] = Wl[i];
    if (threadIdx.x < NCLS) sb[threadIdx.x] = bl[threadIdx.x];
    __syncthreads();

    int gw = (blockIdx.x * blockDim.x + threadIdx.x) >> 5;
    if (gw >= NN) return;
    int lane = threadIdx.x & 31;

    int cfull = g_cnt[gw];
    float di = rsqrtf((float)(cfull + 1));
    float wself = di * di;
    int cnt = min(cfull, SLOTS);
    const size_t base = (size_t)gw * SLOTS;

    unsigned int rw = *reinterpret_cast<const unsigned int*>(m + (size_t)gw * H1 + lane * 2);
    float2 f = h2f(rw);
    float2 acc = make_float2(f.x * wself, f.y * wself);

    for (int j0 = 0; j0 < cnt; j0 += 32) {
        int n = min(32, cnt - j0);
        int s = 0; unsigned int wh = 0; float w = 0.f;
        if (lane < n) {
            s = g_esrc[base + j0 + lane];
            w = dinv_of(s) * di;
            wh = packh2(w, w);
        }
        int t = 0;
        for (; t + 4 <= n; t += 4) {
            int s0 = __shfl_sync(0xffffffffu, s, t);
            int s1 = __shfl_sync(0xffffffffu, s, t + 1);
            int s2 = __shfl_sync(0xffffffffu, s, t + 2);
            int s3 = __shfl_sync(0xffffffffu, s, t + 3);
            unsigned int w0 = __shfl_sync(0xffffffffu, wh, t);
            unsigned int w1 = __shfl_sync(0xffffffffu, wh, t + 1);
            unsigned int w2 = __shfl_sync(0xffffffffu, wh, t + 2);
            unsigned int w3 = __shfl_sync(0xffffffffu, wh, t + 3);
            unsigned int u0 = *reinterpret_cast<const unsigned int*>(m + (size_t)s0 * H1 + lane * 2);
            unsigned int u1 = *reinterpret_cast<const unsigned int*>(m + (size_t)s1 * H1 + lane * 2);
            unsigned int u2 = *reinterpret_cast<const unsigned int*>(m + (size_t)s2 * H1 + lane * 2);
            unsigned int u3 = *reinterpret_cast<const unsigned int*>(m + (size_t)s3 * H1 + lane * 2);
            __half2 p = __hmul2(u2h2(u0), u2h2(w0));
            p = __hfma2(u2h2(u1), u2h2(w1), p);
            p = __hfma2(u2h2(u2), u2h2(w2), p);
            p = __hfma2(u2h2(u3), u2h2(w3), p);
            float2 q = __half22float2(p);
            acc.x += q.x; acc.y += q.y;
        }
        for (; t < n; ++t) {
            int   st = __shfl_sync(0xffffffffu, s, t);
            float wt = __shfl_sync(0xffffffffu, w, t);
            unsigned int u = *reinterpret_cast<const unsigned int*>(m + (size_t)st * H1 + lane * 2);
            float2 a0 = h2f(u);
            acc.x += a0.x * wt; acc.y += a0.y * wt;
        }
    }

    float2 bb = *reinterpret_cast<const float2*>(&b2[lane * 2]);
    float h0 = fmaxf(acc.x + bb.x, 0.f);
    float h1 = fmaxf(acc.y + bb.y, 0.f);

    float logit[NCLS];
#pragma unroll
    for (int c = 0; c < NCLS; c++) {
        float p = h0 * sW[(lane * 2) * NCLS + c] + h1 * sW[(lane * 2 + 1) * NCLS + c];
#pragma unroll
        for (int o = 16; o; o >>= 1) p += __shfl_xor_sync(0xffffffffu, p, o);
        logit[c] = p + sb[c];
    }
    float mx = logit[0];
#pragma unroll
    for (int c = 1; c < NCLS; c++) mx = fmaxf(mx, logit[c]);
    float se = 0.f;
#pragma unroll
    for (int c = 0; c < NCLS; c++) se += expf(logit[c] - mx);
    float lse = mx + logf(se);
    if (lane < NCLS) out[(size_t)gw * NCLS + lane] = logit[lane] - lse;
}

// ---------------------------------------------------------------------------
// Launcher: convert_init(1) -> gemm1(2); fill(3) on side stream;
// gather_act(4) [profiled slot], gemm2(5), gather_final(6).
// ---------------------------------------------------------------------------
extern "C" void kernel_launch(void* const* d_in, const int* in_sizes, int n_in,
                              void* d_out, int out_size) {
    const float* x  = (const float*)d_in[0];
    const void*  ei = d_in[1];
    const float* W1 = (const float*)d_in[2];
    const float* b1 = (const float*)d_in[3];
    const float* W2 = (const float*)d_in[4];
    const float* b2 = (const float*)d_in[5];
    const float* Wl = (const float*)d_in[6];
    const float* bl = (const float*)d_in[7];
    float* out = (float*)d_out;
    const int E = in_sizes[1] / 2;

    __half* p_m1  = nullptr; cudaGetSymbolAddress((void**)&p_m1,  g_m1h);
    __half* p_m1a = nullptr; cudaGetSymbolAddress((void**)&p_m1a, g_m1act);
    __half* p_m2  = nullptr; cudaGetSymbolAddress((void**)&p_m2,  g_m2h);

    static cudaStream_t s_csr = nullptr;
    static cudaEvent_t  ev_fork = nullptr, ev_join = nullptr;
    if (s_csr == nullptr) {
        cudaStreamCreateWithFlags(&s_csr, cudaStreamNonBlocking);
        cudaEventCreateWithFlags(&ev_fork, cudaEventDisableTiming);
        cudaEventCreateWithFlags(&ev_join, cudaEventDisableTiming);
        cudaFuncSetAttribute(gemm1_pipe_kernel,
                             cudaFuncAttributeMaxDynamicSharedMemorySize, G1_SMEM);
    }

    // (1) convert weights + zero counters + detect dtype
    convert_init_kernel<<<NB, 256>>>(W1, W2, ei);
    cudaEventRecord(ev_fork, 0);               // fill needs zeroed counters

    // (2) GEMM1 on main stream
    gemm1_pipe_kernel<<<NPAD / 128, 256, G1_SMEM>>>(x, p_m1, NN);

    // (3) bucket fill on side stream, overlapped with GEMM1
    cudaStreamWaitEvent(s_csr, ev_fork, 0);
    fill_kernel<<<(E + 255) / 256, 256, 0, s_csr>>>(ei, E);
    cudaEventRecord(ev_join, s_csr);

    // join: gather needs both GEMM1 output and edge buckets
    cudaStreamWaitEvent(0, ev_join, 0);

    // (4) gather1 + bias + relu  [ncu-profiled slot]
    gather_act_kernel<<<(NN * 32 + 255) / 256, 256>>>(p_m1, b1, p_m1a);

    // (5) GEMM2, (6) gather2 + classifier + log_softmax
    gemm2_pipe_kernel<<<NPAD / 128, 256>>>(p_m1a, p_m2);
    gather_final_kernel<<<(NN + 7) / 8, 256>>>(p_m2, b2, Wl, bl, out);
}